// round 1
// baseline (speedup 1.0000x reference)
#include <cuda_runtime.h>
#include <cstdint>
#include <cstddef>
#include <math.h>

// Problem constants
#define BB 4
#define NN 256
#define FF 1024
#define HH 16
#define KK 128
#define DD 64
#define HID 4096
#define TAB 32

// ---------------- scratch (device globals; no allocation) ----------------
__device__ float g_S[(size_t)BB * HH * NN * NN];     // bias -> scores -> softmax weights (16.8MB)
__device__ float g_q[(size_t)BB * HH * NN * DD];     // [B,H,N,D]
__device__ float g_k[(size_t)BB * HH * NN * DD];
__device__ float g_v[(size_t)BB * HH * NN * DD];
__device__ float g_attn[(size_t)BB * NN * FF];       // [B,N,F] attention concat
__device__ float g_tmp[(size_t)BB * NN * FF];        // projection outputs
__device__ float g_x1[(size_t)BB * NN * FF];         // post-LN1
__device__ float g_hid[(size_t)BB * NN * HID];       // FFN hidden (16.8MB)
__device__ float g_t1[TAB * HH];                     // precomputed sp-embedding @ w1_sp + b1

// ---------------- T1 precompute: T1[sp][h] = sum_k table[sp,k]*w1[k,h] + b1[h] --------
__global__ void t1_kernel(const float* __restrict__ dist_table,
                          const float* __restrict__ mlp_w1,
                          const float* __restrict__ mlp_b1,
                          float* __restrict__ t1) {
    int t = threadIdx.x;            // 512 threads
    int sp = t >> 4, h = t & 15;
    float s = mlp_b1[h];
    for (int k = 0; k < KK; k++)
        s += dist_table[sp * KK + k] * mlp_w1[k * HH + h];
    t1[t] = s;
}

// ---------------- bias kernel: writes attn_bias into g_S as [B,H,N,N] ----------------
__global__ void bias_kernel(const int* __restrict__ sp_dist,
                            const float* __restrict__ rd_dist,
                            const float* __restrict__ g_means,
                            const float* __restrict__ g_stds,
                            const float* __restrict__ g_mulp,
                            const float* __restrict__ g_biasp,
                            const float* __restrict__ mlp_w1,
                            const float* __restrict__ mlp_w2,
                            const float* __restrict__ mlp_b2,
                            const float* __restrict__ t1,
                            float* __restrict__ S) {
    __shared__ float w1r[KK][HH];      // rd-half of mlp_w1 (rows 128..255)
    __shared__ float t1s[TAB][HH];
    __shared__ float w2s[HH][HH];
    __shared__ float mean_s[KK], istd_s[KK], coef_s[KK];
    __shared__ float b2s[HH];

    int t = threadIdx.x;   // 256
    for (int idx = t; idx < KK * HH; idx += 256)
        w1r[idx >> 4][idx & 15] = mlp_w1[(KK + (idx >> 4)) * HH + (idx & 15)];
    for (int idx = t; idx < TAB * HH; idx += 256)
        t1s[idx >> 4][idx & 15] = t1[idx];
    if (t < HH * HH) w2s[t >> 4][t & 15] = mlp_w2[t];
    if (t < KK) {
        float s = fabsf(g_stds[t]) + 0.01f;
        istd_s[t] = 1.0f / s;
        coef_s[t] = 1.0f / (sqrtf(2.0f * 3.14159f) * s);
        mean_s[t] = g_means[t];
    }
    if (t < HH) b2s[t] = mlp_b2[t];
    __syncthreads();

    int bi = blockIdx.x;                    // b*N + i
    int j = t;
    size_t idx = (size_t)bi * NN + j;
    int sp = sp_dist[idx];
    float rd = rd_dist[idx];
    float x = g_mulp[0] * rd + g_biasp[0];

    float acc[HH];
#pragma unroll
    for (int h = 0; h < HH; h++) acc[h] = t1s[sp][h];

    for (int k = 0; k < KK; k++) {
        float dd = (x - mean_s[k]) * istd_s[k];
        float g = expf(-0.5f * dd * dd) * coef_s[k];
#pragma unroll
        for (int h = 0; h < HH; h++) acc[h] += g * w1r[k][h];
    }
    // exact gelu
#pragma unroll
    for (int h = 0; h < HH; h++) {
        float a = acc[h];
        acc[h] = 0.5f * a * (1.0f + erff(a * 0.70710678118654752f));
    }

    int b = bi >> 8, i = bi & 255;
#pragma unroll
    for (int h2 = 0; h2 < HH; h2++) {
        float o = b2s[h2];
#pragma unroll
        for (int h = 0; h < HH; h++) o += acc[h] * w2s[h][h2];
        S[(((size_t)(b * HH + h2) * NN + i) * NN) + j] = o;
    }
}

// ---------------- SGEMM 128x128x8, 256 threads, 8x8 per thread ----------------
// C = A[M,K] @ B[K,N] + bias ; MODE 0: plain, 1: relu, 2: qkv remap [B,H,N,D] with scale
template <int MODE>
__global__ void sgemm(const float* __restrict__ A, const float* __restrict__ B,
                      const float* __restrict__ bias, float* __restrict__ C,
                      int M, int N, int K, float scale) {
    __shared__ float As[8][128];
    __shared__ float Bs[8][128];
    int t = threadIdx.x;
    int bm = blockIdx.y * 128, bn = blockIdx.x * 128;
    int tx = t & 15, ty = t >> 4;

    float acc[8][8];
#pragma unroll
    for (int i = 0; i < 8; i++)
#pragma unroll
        for (int j = 0; j < 8; j++) acc[i][j] = 0.f;

    int arow = t >> 1, acol = (t & 1) * 4;
    int brow = t >> 5, bcol = (t & 31) * 4;
    const float* Ag = A + (size_t)(bm + arow) * K + acol;
    const float* Bg = B + (size_t)brow * N + bn + bcol;

    for (int k0 = 0; k0 < K; k0 += 8) {
        float4 av = *(const float4*)(Ag + k0);
        As[acol + 0][arow] = av.x;
        As[acol + 1][arow] = av.y;
        As[acol + 2][arow] = av.z;
        As[acol + 3][arow] = av.w;
        float4 bv = *(const float4*)(Bg + (size_t)k0 * N);
        *(float4*)&Bs[brow][bcol] = bv;
        __syncthreads();
#pragma unroll
        for (int kk = 0; kk < 8; kk++) {
            float4 a0 = *(float4*)&As[kk][ty * 4];
            float4 a1 = *(float4*)&As[kk][64 + ty * 4];
            float4 b0 = *(float4*)&Bs[kk][tx * 4];
            float4 b1 = *(float4*)&Bs[kk][64 + tx * 4];
            float ar[8] = {a0.x, a0.y, a0.z, a0.w, a1.x, a1.y, a1.z, a1.w};
            float br[8] = {b0.x, b0.y, b0.z, b0.w, b1.x, b1.y, b1.z, b1.w};
#pragma unroll
            for (int i = 0; i < 8; i++)
#pragma unroll
                for (int j = 0; j < 8; j++) acc[i][j] += ar[i] * br[j];
        }
        __syncthreads();
    }

#pragma unroll
    for (int i = 0; i < 8; i++) {
        int m = bm + ((i < 4) ? (ty * 4 + i) : (64 + ty * 4 + i - 4));
#pragma unroll
        for (int jg = 0; jg < 2; jg++) {
            int n = bn + jg * 64 + tx * 4;
            float r[4];
#pragma unroll
            for (int c = 0; c < 4; c++) r[c] = acc[i][jg * 4 + c] + bias[n + c];
            if (MODE == 1) {
#pragma unroll
                for (int c = 0; c < 4; c++) r[c] = fmaxf(r[c], 0.f);
            }
            if (MODE == 2) {
                int b = m >> 8, ii = m & 255;
#pragma unroll
                for (int c = 0; c < 4; c++) {
                    int nn = n + c;
                    int h = nn >> 6, d = nn & 63;
                    C[(((size_t)(b * HH + h) * NN + ii) * DD) + d] = r[c] * scale;
                }
            } else {
                float4 v = {r[0], r[1], r[2], r[3]};
                *(float4*)&C[(size_t)m * N + n] = v;
            }
        }
    }
}

// ---------------- scores: S[b,h,i,j] = Q[b,h,i,:].K[b,h,j,:] + S(bias, in place) ----
__global__ void scores_kernel(const float* __restrict__ Q, const float* __restrict__ Kp,
                              float* __restrict__ S) {
    int bh = blockIdx.z;
    int i0 = blockIdx.y * 64, j0 = blockIdx.x * 64;
    const float* Qg = Q + (size_t)bh * NN * DD;
    const float* Kg = Kp + (size_t)bh * NN * DD;
    float* Sg = S + (size_t)bh * NN * NN;

    __shared__ float Qs[64][68];  // [d][i], padded
    __shared__ float Ks[64][68];  // [d][j]
    int t = threadIdx.x;          // 256
#pragma unroll
    for (int r = 0; r < 4; r++) {
        int idx = t + r * 256;
        int row = idx >> 4;
        int d4 = (idx & 15) * 4;
        float4 qv = *(const float4*)(Qg + (size_t)(i0 + row) * DD + d4);
        Qs[d4 + 0][row] = qv.x; Qs[d4 + 1][row] = qv.y;
        Qs[d4 + 2][row] = qv.z; Qs[d4 + 3][row] = qv.w;
        float4 kv = *(const float4*)(Kg + (size_t)(j0 + row) * DD + d4);
        Ks[d4 + 0][row] = kv.x; Ks[d4 + 1][row] = kv.y;
        Ks[d4 + 2][row] = kv.z; Ks[d4 + 3][row] = kv.w;
    }
    __syncthreads();

    int tx = t & 15, ty = t >> 4;
    float acc[4][4];
#pragma unroll
    for (int i = 0; i < 4; i++)
#pragma unroll
        for (int j = 0; j < 4; j++) acc[i][j] = 0.f;

#pragma unroll 8
    for (int d = 0; d < 64; d++) {
        float4 qr = *(float4*)&Qs[d][ty * 4];
        float4 kr = *(float4*)&Ks[d][tx * 4];
        float qa[4] = {qr.x, qr.y, qr.z, qr.w};
        float ka[4] = {kr.x, kr.y, kr.z, kr.w};
#pragma unroll
        for (int i = 0; i < 4; i++)
#pragma unroll
            for (int j = 0; j < 4; j++) acc[i][j] += qa[i] * ka[j];
    }
#pragma unroll
    for (int i = 0; i < 4; i++) {
        size_t off = (size_t)(i0 + ty * 4 + i) * NN + j0 + tx * 4;
        float4 bv = *(float4*)(Sg + off);
        bv.x += acc[i][0]; bv.y += acc[i][1];
        bv.z += acc[i][2]; bv.w += acc[i][3];
        *(float4*)(Sg + off) = bv;
    }
}

// ---------------- softmax over j (row of 256), in place ----------------
__global__ void softmax_kernel(float* __restrict__ S) {
    size_t row = blockIdx.x;
    float* p = S + row * NN;
    int t = threadIdx.x;
    __shared__ float red[256];
    float v = p[t];
    red[t] = v;
    __syncthreads();
#pragma unroll
    for (int s = 128; s > 0; s >>= 1) {
        if (t < s) red[t] = fmaxf(red[t], red[t + s]);
        __syncthreads();
    }
    float m = red[0];
    __syncthreads();
    float e = expf(v - m);
    red[t] = e;
    __syncthreads();
#pragma unroll
    for (int s = 128; s > 0; s >>= 1) {
        if (t < s) red[t] += red[t + s];
        __syncthreads();
    }
    p[t] = e / red[0];
}

// ---------------- PV: attn[b,i,h*64+d] = sum_j W[b,h,i,j] V[b,h,j,d] ----------------
__global__ void pv_kernel(const float* __restrict__ W, const float* __restrict__ V,
                          float* __restrict__ O) {
    int bh = blockIdx.y;
    int b = bh >> 4, h = bh & 15;
    int i0 = blockIdx.x * 64;
    const float* Wg = W + (size_t)bh * NN * NN;
    const float* Vg = V + (size_t)bh * NN * DD;

    __shared__ float Ws[64][68];  // [j][i]
    __shared__ float Vs[64][68];  // [j][d]
    int t = threadIdx.x, tx = t & 15, ty = t >> 4;
    float acc[4][4];
#pragma unroll
    for (int i = 0; i < 4; i++)
#pragma unroll
        for (int j = 0; j < 4; j++) acc[i][j] = 0.f;

    for (int jc = 0; jc < 4; jc++) {
        int j0 = jc * 64;
#pragma unroll
        for (int r = 0; r < 4; r++) {
            int idx = t + r * 256;
            int row = idx >> 4;
            int c4 = (idx & 15) * 4;
            float4 wv = *(const float4*)(Wg + (size_t)(i0 + row) * NN + j0 + c4);
            Ws[c4 + 0][row] = wv.x; Ws[c4 + 1][row] = wv.y;
            Ws[c4 + 2][row] = wv.z; Ws[c4 + 3][row] = wv.w;
            float4 vv = *(const float4*)(Vg + (size_t)(j0 + row) * DD + c4);
            *(float4*)&Vs[row][c4] = vv;
        }
        __syncthreads();
#pragma unroll 8
        for (int jj = 0; jj < 64; jj++) {
            float4 wr = *(float4*)&Ws[jj][ty * 4];
            float4 vr = *(float4*)&Vs[jj][tx * 4];
            float wa[4] = {wr.x, wr.y, wr.z, wr.w};
            float va[4] = {vr.x, vr.y, vr.z, vr.w};
#pragma unroll
            for (int i = 0; i < 4; i++)
#pragma unroll
                for (int j = 0; j < 4; j++) acc[i][j] += wa[i] * va[j];
        }
        __syncthreads();
    }
#pragma unroll
    for (int i = 0; i < 4; i++) {
        size_t off = (size_t)(b * NN + i0 + ty * 4 + i) * FF + h * DD + tx * 4;
        float4 v = {acc[i][0], acc[i][1], acc[i][2], acc[i][3]};
        *(float4*)&O[off] = v;
    }
}

// ---------------- out = LayerNorm(A + B) * g + be ----------------
__global__ void add_ln_kernel(const float* __restrict__ A, const float* __restrict__ Bv,
                              const float* __restrict__ g, const float* __restrict__ be,
                              float* __restrict__ out) {
    int row = blockIdx.x, t = threadIdx.x;
    const float* a = A + (size_t)row * FF;
    const float* b = Bv + (size_t)row * FF;
    __shared__ float red[256];
    float v[4];
    float s = 0.f;
#pragma unroll
    for (int k = 0; k < 4; k++) {
        int c = t + k * 256;
        v[k] = a[c] + b[c];
        s += v[k];
    }
    red[t] = s;
    __syncthreads();
#pragma unroll
    for (int st = 128; st > 0; st >>= 1) {
        if (t < st) red[t] += red[t + st];
        __syncthreads();
    }
    float mean = red[0] * (1.0f / FF);
    __syncthreads();
    float sq = 0.f;
#pragma unroll
    for (int k = 0; k < 4; k++) {
        float d = v[k] - mean;
        sq += d * d;
    }
    red[t] = sq;
    __syncthreads();
#pragma unroll
    for (int st = 128; st > 0; st >>= 1) {
        if (t < st) red[t] += red[t + st];
        __syncthreads();
    }
    float inv = rsqrtf(red[0] * (1.0f / FF) + 1e-5f);
#pragma unroll
    for (int k = 0; k < 4; k++) {
        int c = t + k * 256;
        out[(size_t)row * FF + c] = (v[k] - mean) * inv * g[c] + be[c];
    }
}

// ---------------- launch ----------------
extern "C" void kernel_launch(void* const* d_in, const int* in_sizes, int n_in,
                              void* d_out, int out_size) {
    const float* nfeat      = (const float*)d_in[0];
    const int*   sp_dist    = (const int*)d_in[1];
    const float* rd_dist    = (const float*)d_in[2];
    const float* dist_table = (const float*)d_in[3];
    const float* g_means    = (const float*)d_in[4];
    const float* g_stds     = (const float*)d_in[5];
    const float* g_mul      = (const float*)d_in[6];
    const float* g_biasv    = (const float*)d_in[7];
    const float* mlp_w1     = (const float*)d_in[8];
    const float* mlp_b1     = (const float*)d_in[9];
    const float* mlp_w2     = (const float*)d_in[10];
    const float* mlp_b2     = (const float*)d_in[11];
    const float* wq = (const float*)d_in[12];  const float* bq = (const float*)d_in[13];
    const float* wk = (const float*)d_in[14];  const float* bk = (const float*)d_in[15];
    const float* wv = (const float*)d_in[16];  const float* bv = (const float*)d_in[17];
    const float* wo = (const float*)d_in[18];  const float* bo = (const float*)d_in[19];
    const float* ffn_w1 = (const float*)d_in[20]; const float* ffn_b1 = (const float*)d_in[21];
    const float* ffn_w2 = (const float*)d_in[22]; const float* ffn_b2 = (const float*)d_in[23];
    const float* ln1_g = (const float*)d_in[24]; const float* ln1_b = (const float*)d_in[25];
    const float* ln2_g = (const float*)d_in[26]; const float* ln2_b = (const float*)d_in[27];

    void *pS, *pQ, *pK, *pV, *pAttn, *pTmp, *pX1, *pHid, *pT1;
    cudaGetSymbolAddress(&pS, g_S);
    cudaGetSymbolAddress(&pQ, g_q);
    cudaGetSymbolAddress(&pK, g_k);
    cudaGetSymbolAddress(&pV, g_v);
    cudaGetSymbolAddress(&pAttn, g_attn);
    cudaGetSymbolAddress(&pTmp, g_tmp);
    cudaGetSymbolAddress(&pX1, g_x1);
    cudaGetSymbolAddress(&pHid, g_hid);
    cudaGetSymbolAddress(&pT1, g_t1);

    float* S = (float*)pS; float* Q = (float*)pQ; float* Kb = (float*)pK;
    float* V = (float*)pV; float* At = (float*)pAttn; float* Tm = (float*)pTmp;
    float* X1 = (float*)pX1; float* Hd = (float*)pHid; float* T1 = (float*)pT1;

    // 1. dist-encoder
    t1_kernel<<<1, 512>>>(dist_table, mlp_w1, mlp_b1, T1);
    bias_kernel<<<BB * NN, 256>>>(sp_dist, rd_dist, g_means, g_stds, g_mul, g_biasv,
                                  mlp_w1, mlp_w2, mlp_b2, T1, S);

    // 2. QKV projections (q scaled by sqrt(D)=8 per reference)
    sgemm<2><<<dim3(8, 8), 256>>>(nfeat, wq, bq, Q, BB * NN, FF, FF, 8.0f);
    sgemm<2><<<dim3(8, 8), 256>>>(nfeat, wk, bk, Kb, BB * NN, FF, FF, 1.0f);
    sgemm<2><<<dim3(8, 8), 256>>>(nfeat, wv, bv, V, BB * NN, FF, FF, 1.0f);

    // 3. attention
    scores_kernel<<<dim3(4, 4, BB * HH), 256>>>(Q, Kb, S);
    softmax_kernel<<<BB * HH * NN, 256>>>(S);
    pv_kernel<<<dim3(4, BB * HH), 256>>>(S, V, At);

    // 4. output projection + LN1
    sgemm<0><<<dim3(8, 8), 256>>>(At, wo, bo, Tm, BB * NN, FF, FF, 1.0f);
    add_ln_kernel<<<BB * NN, 256>>>(nfeat, Tm, ln1_g, ln1_b, X1);

    // 5. FFN + LN2
    sgemm<1><<<dim3(32, 8), 256>>>(X1, ffn_w1, ffn_b1, Hd, BB * NN, HID, FF, 1.0f);
    sgemm<0><<<dim3(8, 8), 256>>>(Hd, ffn_w2, ffn_b2, Tm, BB * NN, FF, HID, 1.0f);
    add_ln_kernel<<<BB * NN, 256>>>(X1, Tm, ln2_g, ln2_b, (float*)d_out);
}

// round 2
// speedup vs baseline: 3.5678x; 3.5678x over previous
#include <cuda_runtime.h>
#include <cstdint>
#include <cstddef>
#include <math.h>

// Problem constants
#define BB 4
#define NN 256
#define FF 1024
#define HH 16
#define KK 128
#define DD 64
#define HID 4096
#define TAB 32

// ---------------- scratch (device globals; no allocation) ----------------
__device__ float g_S[(size_t)BB * HH * NN * NN];     // bias -> scores -> softmax weights
__device__ float g_q[(size_t)BB * HH * NN * DD];     // [B,H,N,D]
__device__ float g_k[(size_t)BB * HH * NN * DD];
__device__ float g_v[(size_t)BB * HH * NN * DD];
__device__ float g_attn[(size_t)BB * NN * FF];
__device__ float g_tmp[(size_t)BB * NN * FF];
__device__ float g_x1[(size_t)BB * NN * FF];
__device__ float g_hid[(size_t)BB * NN * HID];
__device__ float g_t1[TAB * HH];

// ---------------- T1 precompute ----------------
__global__ void t1_kernel(const float* __restrict__ dist_table,
                          const float* __restrict__ mlp_w1,
                          const float* __restrict__ mlp_b1,
                          float* __restrict__ t1) {
    int t = threadIdx.x;            // 512 threads
    int sp = t >> 4, h = t & 15;
    float s = mlp_b1[h];
    for (int k = 0; k < KK; k++)
        s += dist_table[sp * KK + k] * mlp_w1[k * HH + h];
    t1[t] = s;
}

// ---------------- bias kernel ----------------
__global__ void bias_kernel(const int* __restrict__ sp_dist,
                            const float* __restrict__ rd_dist,
                            const float* __restrict__ g_means,
                            const float* __restrict__ g_stds,
                            const float* __restrict__ g_mulp,
                            const float* __restrict__ g_biasp,
                            const float* __restrict__ mlp_w1,
                            const float* __restrict__ mlp_w2,
                            const float* __restrict__ mlp_b2,
                            const float* __restrict__ t1,
                            float* __restrict__ S) {
    __shared__ float w1r[KK][HH];
    __shared__ float t1s[TAB][HH];
    __shared__ float w2s[HH][HH];
    __shared__ float mean_s[KK], istd_s[KK], coef_s[KK];
    __shared__ float b2s[HH];

    int t = threadIdx.x;   // 256
    for (int idx = t; idx < KK * HH; idx += 256)
        w1r[idx >> 4][idx & 15] = mlp_w1[(KK + (idx >> 4)) * HH + (idx & 15)];
    for (int idx = t; idx < TAB * HH; idx += 256)
        t1s[idx >> 4][idx & 15] = t1[idx];
    if (t < HH * HH) w2s[t >> 4][t & 15] = mlp_w2[t];
    if (t < KK) {
        float s = fabsf(g_stds[t]) + 0.01f;
        istd_s[t] = 1.0f / s;
        coef_s[t] = 1.0f / (sqrtf(2.0f * 3.14159f) * s);
        mean_s[t] = g_means[t];
    }
    if (t < HH) b2s[t] = mlp_b2[t];
    __syncthreads();

    int bi = blockIdx.x;                    // b*N + i
    int j = t;
    size_t idx = (size_t)bi * NN + j;
    int sp = sp_dist[idx];
    float rd = rd_dist[idx];
    float x = g_mulp[0] * rd + g_biasp[0];

    float acc[HH];
#pragma unroll
    for (int h = 0; h < HH; h++) acc[h] = t1s[sp][h];

    for (int k = 0; k < KK; k++) {
        float dd = (x - mean_s[k]) * istd_s[k];
        float g = expf(-0.5f * dd * dd) * coef_s[k];
#pragma unroll
        for (int h = 0; h < HH; h++) acc[h] += g * w1r[k][h];
    }
#pragma unroll
    for (int h = 0; h < HH; h++) {
        float a = acc[h];
        acc[h] = 0.5f * a * (1.0f + erff(a * 0.70710678118654752f));
    }

    int b = bi >> 8, i = bi & 255;
#pragma unroll
    for (int h2 = 0; h2 < HH; h2++) {
        float o = b2s[h2];
#pragma unroll
        for (int h = 0; h < HH; h++) o += acc[h] * w2s[h][h2];
        S[(((size_t)(b * HH + h2) * NN + i) * NN) + j] = o;
    }
}

// ---------------- TF32 tensor-core GEMM ----------------
// C[M,N] = A[M,K] @ B[K,N] + bias. 64x64 tile, BK=32, 128 threads (2x2 warps,
// 32x32 per warp). cp.async double-buffered. MODE 0 plain, 1 relu, 2 qkv remap.
__device__ __forceinline__ unsigned f2tf(float f) {
    unsigned u;
    asm("cvt.rna.tf32.f32 %0, %1;" : "=r"(u) : "f"(f));
    return u;
}

template <int MODE>
__global__ void __launch_bounds__(128) mma_gemm(
    const float* __restrict__ A, const float* __restrict__ B,
    const float* __restrict__ bias, float* __restrict__ C,
    int M, int N, int K, float scale) {
    __shared__ float As[2][64][36];   // [k-pad 36: bank=(4m+k)%32 conflict-free]
    __shared__ float Bs[2][32][68];   // [n-pad 68: bank=(4k+n)%32 conflict-free]

    int t = threadIdx.x;
    int warp = t >> 5, lane = t & 31;
    int g = lane >> 2, q = lane & 3;
    int wm = (warp >> 1) * 32, wn = (warp & 1) * 32;
    int m0 = blockIdx.y * 64, n0 = blockIdx.x * 64;

    float c[2][4][4];
#pragma unroll
    for (int i = 0; i < 2; i++)
#pragma unroll
        for (int j = 0; j < 4; j++)
#pragma unroll
            for (int e = 0; e < 4; e++) c[i][j][e] = 0.f;

    const int KT = K / 32;

    // prefetch helper (inlined twice)
#define LOAD_TILE(bufi, k0)                                                       \
    do {                                                                          \
        _Pragma("unroll")                                                         \
        for (int i_ = 0; i_ < 4; i_++) {                                          \
            int id = t + i_ * 128;                                                \
            int row = id >> 3, c4 = id & 7;                                       \
            const float* src = A + (size_t)(m0 + row) * K + (k0) + c4 * 4;        \
            unsigned dst = (unsigned)__cvta_generic_to_shared(&As[bufi][row][c4 * 4]); \
            asm volatile("cp.async.ca.shared.global [%0], [%1], 16;\n" ::"r"(dst), "l"(src)); \
        }                                                                         \
        _Pragma("unroll")                                                         \
        for (int i_ = 0; i_ < 4; i_++) {                                          \
            int id = t + i_ * 128;                                                \
            int row = id >> 4, c4 = id & 15;                                      \
            const float* src = B + (size_t)((k0) + row) * N + n0 + c4 * 4;        \
            unsigned dst = (unsigned)__cvta_generic_to_shared(&Bs[bufi][row][c4 * 4]); \
            asm volatile("cp.async.ca.shared.global [%0], [%1], 16;\n" ::"r"(dst), "l"(src)); \
        }                                                                         \
        asm volatile("cp.async.commit_group;\n" ::);                              \
    } while (0)

    LOAD_TILE(0, 0);

    for (int kt = 0; kt < KT; kt++) {
        int buf = kt & 1;
        if (kt + 1 < KT) {
            LOAD_TILE(buf ^ 1, (kt + 1) * 32);
            asm volatile("cp.async.wait_group 1;\n" ::);
        } else {
            asm volatile("cp.async.wait_group 0;\n" ::);
        }
        __syncthreads();

#pragma unroll
        for (int ks = 0; ks < 4; ks++) {
            unsigned a[2][4], b[4][2];
#pragma unroll
            for (int mt = 0; mt < 2; mt++) {
                int r = wm + mt * 16 + g;
                int k = ks * 8 + q;
                a[mt][0] = f2tf(As[buf][r][k]);
                a[mt][1] = f2tf(As[buf][r + 8][k]);
                a[mt][2] = f2tf(As[buf][r][k + 4]);
                a[mt][3] = f2tf(As[buf][r + 8][k + 4]);
            }
#pragma unroll
            for (int nt = 0; nt < 4; nt++) {
                int n = wn + nt * 8 + g;
                int k = ks * 8 + q;
                b[nt][0] = f2tf(Bs[buf][k][n]);
                b[nt][1] = f2tf(Bs[buf][k + 4][n]);
            }
#pragma unroll
            for (int mt = 0; mt < 2; mt++)
#pragma unroll
                for (int nt = 0; nt < 4; nt++)
                    asm volatile(
                        "mma.sync.aligned.m16n8k8.row.col.f32.tf32.tf32.f32 "
                        "{%0,%1,%2,%3},{%4,%5,%6,%7},{%8,%9},{%0,%1,%2,%3};"
                        : "+f"(c[mt][nt][0]), "+f"(c[mt][nt][1]),
                          "+f"(c[mt][nt][2]), "+f"(c[mt][nt][3])
                        : "r"(a[mt][0]), "r"(a[mt][1]), "r"(a[mt][2]), "r"(a[mt][3]),
                          "r"(b[nt][0]), "r"(b[nt][1]));
        }
        __syncthreads();
    }
#undef LOAD_TILE

    // epilogue
#pragma unroll
    for (int mt = 0; mt < 2; mt++)
#pragma unroll
        for (int nt = 0; nt < 4; nt++)
#pragma unroll
            for (int e = 0; e < 4; e++) {
                int row = m0 + wm + mt * 16 + g + ((e >= 2) ? 8 : 0);
                int col = n0 + wn + nt * 8 + q * 2 + (e & 1);
                float v = c[mt][nt][e] + bias[col];
                if (MODE == 1) v = fmaxf(v, 0.f);
                if (MODE == 2) {
                    int b_ = row >> 8, ii = row & 255, h = col >> 6, d = col & 63;
                    C[(((size_t)(b_ * HH + h) * NN + ii) * DD) + d] = v * scale;
                } else {
                    C[(size_t)row * N + col] = v;
                }
            }
}

// ---------------- scores ----------------
__global__ void scores_kernel(const float* __restrict__ Q, const float* __restrict__ Kp,
                              float* __restrict__ S) {
    int bh = blockIdx.z;
    int i0 = blockIdx.y * 64, j0 = blockIdx.x * 64;
    const float* Qg = Q + (size_t)bh * NN * DD;
    const float* Kg = Kp + (size_t)bh * NN * DD;
    float* Sg = S + (size_t)bh * NN * NN;

    __shared__ float Qs[64][68];
    __shared__ float Ks[64][68];
    int t = threadIdx.x;          // 256
#pragma unroll
    for (int r = 0; r < 4; r++) {
        int idx = t + r * 256;
        int row = idx >> 4;
        int d4 = (idx & 15) * 4;
        float4 qv = *(const float4*)(Qg + (size_t)(i0 + row) * DD + d4);
        Qs[d4 + 0][row] = qv.x; Qs[d4 + 1][row] = qv.y;
        Qs[d4 + 2][row] = qv.z; Qs[d4 + 3][row] = qv.w;
        float4 kv = *(const float4*)(Kg + (size_t)(j0 + row) * DD + d4);
        Ks[d4 + 0][row] = kv.x; Ks[d4 + 1][row] = kv.y;
        Ks[d4 + 2][row] = kv.z; Ks[d4 + 3][row] = kv.w;
    }
    __syncthreads();

    int tx = t & 15, ty = t >> 4;
    float acc[4][4];
#pragma unroll
    for (int i = 0; i < 4; i++)
#pragma unroll
        for (int j = 0; j < 4; j++) acc[i][j] = 0.f;

#pragma unroll 8
    for (int d = 0; d < 64; d++) {
        float4 qr = *(float4*)&Qs[d][ty * 4];
        float4 kr = *(float4*)&Ks[d][tx * 4];
        float qa[4] = {qr.x, qr.y, qr.z, qr.w};
        float ka[4] = {kr.x, kr.y, kr.z, kr.w};
#pragma unroll
        for (int i = 0; i < 4; i++)
#pragma unroll
            for (int j = 0; j < 4; j++) acc[i][j] += qa[i] * ka[j];
    }
#pragma unroll
    for (int i = 0; i < 4; i++) {
        size_t off = (size_t)(i0 + ty * 4 + i) * NN + j0 + tx * 4;
        float4 bv = *(float4*)(Sg + off);
        bv.x += acc[i][0]; bv.y += acc[i][1];
        bv.z += acc[i][2]; bv.w += acc[i][3];
        *(float4*)(Sg + off) = bv;
    }
}

// ---------------- softmax ----------------
__global__ void softmax_kernel(float* __restrict__ S) {
    size_t row = blockIdx.x;
    float* p = S + row * NN;
    int t = threadIdx.x;
    __shared__ float red[256];
    float v = p[t];
    red[t] = v;
    __syncthreads();
#pragma unroll
    for (int s = 128; s > 0; s >>= 1) {
        if (t < s) red[t] = fmaxf(red[t], red[t + s]);
        __syncthreads();
    }
    float m = red[0];
    __syncthreads();
    float e = expf(v - m);
    red[t] = e;
    __syncthreads();
#pragma unroll
    for (int s = 128; s > 0; s >>= 1) {
        if (t < s) red[t] += red[t + s];
        __syncthreads();
    }
    p[t] = e / red[0];
}

// ---------------- PV ----------------
__global__ void pv_kernel(const float* __restrict__ W, const float* __restrict__ V,
                          float* __restrict__ O) {
    int bh = blockIdx.y;
    int b = bh >> 4, h = bh & 15;
    int i0 = blockIdx.x * 64;
    const float* Wg = W + (size_t)bh * NN * NN;
    const float* Vg = V + (size_t)bh * NN * DD;

    __shared__ float Ws[64][68];
    __shared__ float Vs[64][68];
    int t = threadIdx.x, tx = t & 15, ty = t >> 4;
    float acc[4][4];
#pragma unroll
    for (int i = 0; i < 4; i++)
#pragma unroll
        for (int j = 0; j < 4; j++) acc[i][j] = 0.f;

    for (int jc = 0; jc < 4; jc++) {
        int j0 = jc * 64;
#pragma unroll
        for (int r = 0; r < 4; r++) {
            int idx = t + r * 256;
            int row = idx >> 4;
            int c4 = (idx & 15) * 4;
            float4 wv = *(const float4*)(Wg + (size_t)(i0 + row) * NN + j0 + c4);
            Ws[c4 + 0][row] = wv.x; Ws[c4 + 1][row] = wv.y;
            Ws[c4 + 2][row] = wv.z; Ws[c4 + 3][row] = wv.w;
            float4 vv = *(const float4*)(Vg + (size_t)(j0 + row) * DD + c4);
            *(float4*)&Vs[row][c4] = vv;
        }
        __syncthreads();
#pragma unroll 8
        for (int jj = 0; jj < 64; jj++) {
            float4 wr = *(float4*)&Ws[jj][ty * 4];
            float4 vr = *(float4*)&Vs[jj][tx * 4];
            float wa[4] = {wr.x, wr.y, wr.z, wr.w};
            float va[4] = {vr.x, vr.y, vr.z, vr.w};
#pragma unroll
            for (int i = 0; i < 4; i++)
#pragma unroll
                for (int j = 0; j < 4; j++) acc[i][j] += wa[i] * va[j];
        }
        __syncthreads();
    }
#pragma unroll
    for (int i = 0; i < 4; i++) {
        size_t off = (size_t)(b * NN + i0 + ty * 4 + i) * FF + h * DD + tx * 4;
        float4 v = {acc[i][0], acc[i][1], acc[i][2], acc[i][3]};
        *(float4*)&O[off] = v;
    }
}

// ---------------- add + LayerNorm ----------------
__global__ void add_ln_kernel(const float* __restrict__ A, const float* __restrict__ Bv,
                              const float* __restrict__ g, const float* __restrict__ be,
                              float* __restrict__ out) {
    int row = blockIdx.x, t = threadIdx.x;
    const float* a = A + (size_t)row * FF;
    const float* b = Bv + (size_t)row * FF;
    __shared__ float red[256];
    float v[4];
    float s = 0.f;
#pragma unroll
    for (int k = 0; k < 4; k++) {
        int c = t + k * 256;
        v[k] = a[c] + b[c];
        s += v[k];
    }
    red[t] = s;
    __syncthreads();
#pragma unroll
    for (int st = 128; st > 0; st >>= 1) {
        if (t < st) red[t] += red[t + st];
        __syncthreads();
    }
    float mean = red[0] * (1.0f / FF);
    __syncthreads();
    float sq = 0.f;
#pragma unroll
    for (int k = 0; k < 4; k++) {
        float d = v[k] - mean;
        sq += d * d;
    }
    red[t] = sq;
    __syncthreads();
#pragma unroll
    for (int st = 128; st > 0; st >>= 1) {
        if (t < st) red[t] += red[t + st];
        __syncthreads();
    }
    float inv = rsqrtf(red[0] * (1.0f / FF) + 1e-5f);
#pragma unroll
    for (int k = 0; k < 4; k++) {
        int c = t + k * 256;
        out[(size_t)row * FF + c] = (v[k] - mean) * inv * g[c] + be[c];
    }
}

// ---------------- launch ----------------
extern "C" void kernel_launch(void* const* d_in, const int* in_sizes, int n_in,
                              void* d_out, int out_size) {
    const float* nfeat      = (const float*)d_in[0];
    const int*   sp_dist    = (const int*)d_in[1];
    const float* rd_dist    = (const float*)d_in[2];
    const float* dist_table = (const float*)d_in[3];
    const float* g_means    = (const float*)d_in[4];
    const float* g_stds     = (const float*)d_in[5];
    const float* g_mul      = (const float*)d_in[6];
    const float* g_biasv    = (const float*)d_in[7];
    const float* mlp_w1     = (const float*)d_in[8];
    const float* mlp_b1     = (const float*)d_in[9];
    const float* mlp_w2     = (const float*)d_in[10];
    const float* mlp_b2     = (const float*)d_in[11];
    const float* wq = (const float*)d_in[12];  const float* bq = (const float*)d_in[13];
    const float* wk = (const float*)d_in[14];  const float* bk = (const float*)d_in[15];
    const float* wv = (const float*)d_in[16];  const float* bv = (const float*)d_in[17];
    const float* wo = (const float*)d_in[18];  const float* bo = (const float*)d_in[19];
    const float* ffn_w1 = (const float*)d_in[20]; const float* ffn_b1 = (const float*)d_in[21];
    const float* ffn_w2 = (const float*)d_in[22]; const float* ffn_b2 = (const float*)d_in[23];
    const float* ln1_g = (const float*)d_in[24]; const float* ln1_b = (const float*)d_in[25];
    const float* ln2_g = (const float*)d_in[26]; const float* ln2_b = (const float*)d_in[27];

    void *pS, *pQ, *pK, *pV, *pAttn, *pTmp, *pX1, *pHid, *pT1;
    cudaGetSymbolAddress(&pS, g_S);
    cudaGetSymbolAddress(&pQ, g_q);
    cudaGetSymbolAddress(&pK, g_k);
    cudaGetSymbolAddress(&pV, g_v);
    cudaGetSymbolAddress(&pAttn, g_attn);
    cudaGetSymbolAddress(&pTmp, g_tmp);
    cudaGetSymbolAddress(&pX1, g_x1);
    cudaGetSymbolAddress(&pHid, g_hid);
    cudaGetSymbolAddress(&pT1, g_t1);

    float* S = (float*)pS; float* Q = (float*)pQ; float* Kb = (float*)pK;
    float* V = (float*)pV; float* At = (float*)pAttn; float* Tm = (float*)pTmp;
    float* X1 = (float*)pX1; float* Hd = (float*)pHid; float* T1 = (float*)pT1;

    // 1. dist-encoder
    t1_kernel<<<1, 512>>>(dist_table, mlp_w1, mlp_b1, T1);
    bias_kernel<<<BB * NN, 256>>>(sp_dist, rd_dist, g_means, g_stds, g_mul, g_biasv,
                                  mlp_w1, mlp_w2, mlp_b2, T1, S);

    // 2. QKV projections (q scaled by sqrt(D)=8 per reference)
    mma_gemm<2><<<dim3(16, 16), 128>>>(nfeat, wq, bq, Q, BB * NN, FF, FF, 8.0f);
    mma_gemm<2><<<dim3(16, 16), 128>>>(nfeat, wk, bk, Kb, BB * NN, FF, FF, 1.0f);
    mma_gemm<2><<<dim3(16, 16), 128>>>(nfeat, wv, bv, V, BB * NN, FF, FF, 1.0f);

    // 3. attention
    scores_kernel<<<dim3(4, 4, BB * HH), 256>>>(Q, Kb, S);
    softmax_kernel<<<BB * HH * NN, 256>>>(S);
    pv_kernel<<<dim3(4, BB * HH), 256>>>(S, V, At);

    // 4. output projection + LN1
    mma_gemm<0><<<dim3(16, 16), 128>>>(At, wo, bo, Tm, BB * NN, FF, FF, 1.0f);
    add_ln_kernel<<<BB * NN, 256>>>(nfeat, Tm, ln1_g, ln1_b, X1);

    // 5. FFN + LN2
    mma_gemm<1><<<dim3(64, 16), 128>>>(X1, ffn_w1, ffn_b1, Hd, BB * NN, HID, FF, 1.0f);
    mma_gemm<0><<<dim3(16, 16), 128>>>(Hd, ffn_w2, ffn_b2, Tm, BB * NN, FF, HID, 1.0f);
    add_ln_kernel<<<BB * NN, 256>>>(X1, Tm, ln2_g, ln2_b, (float*)d_out);
}

// round 3
// speedup vs baseline: 3.7246x; 1.0439x over previous
#include <cuda_runtime.h>
#include <cstdint>
#include <cstddef>
#include <math.h>

// Problem constants
#define BB 4
#define NN 256
#define FF 1024
#define HH 16
#define KK 128
#define DD 64
#define HID 4096
#define TAB 32

// ---------------- scratch (device globals; no allocation) ----------------
__device__ float g_S[(size_t)BB * HH * NN * NN];
__device__ float g_q[(size_t)BB * HH * NN * DD];
__device__ float g_k[(size_t)BB * HH * NN * DD];
__device__ float g_v[(size_t)BB * HH * NN * DD];
__device__ float g_attn[(size_t)BB * NN * FF];
__device__ float g_x1[(size_t)BB * NN * FF];
__device__ float g_hid[(size_t)BB * NN * HID];
__device__ float g_part[(size_t)4 * BB * NN * FF];   // split-K partials (16MB)
__device__ float g_t1[TAB * HH];

// ---------------- T1 precompute ----------------
__global__ void t1_kernel(const float* __restrict__ dist_table,
                          const float* __restrict__ mlp_w1,
                          const float* __restrict__ mlp_b1,
                          float* __restrict__ t1) {
    int t = threadIdx.x;            // 512 threads
    int sp = t >> 4, h = t & 15;
    float s = mlp_b1[h];
    for (int k = 0; k < KK; k++)
        s += dist_table[sp * KK + k] * mlp_w1[k * HH + h];
    t1[t] = s;
}

// ---------------- bias kernel ----------------
__global__ void bias_kernel(const int* __restrict__ sp_dist,
                            const float* __restrict__ rd_dist,
                            const float* __restrict__ g_means,
                            const float* __restrict__ g_stds,
                            const float* __restrict__ g_mulp,
                            const float* __restrict__ g_biasp,
                            const float* __restrict__ mlp_w1,
                            const float* __restrict__ mlp_w2,
                            const float* __restrict__ mlp_b2,
                            const float* __restrict__ t1,
                            float* __restrict__ S) {
    __shared__ float w1r[KK][HH];
    __shared__ float t1s[TAB][HH];
    __shared__ float w2s[HH][HH];
    __shared__ float mean_s[KK], istd_s[KK], coef_s[KK];
    __shared__ float b2s[HH];

    int t = threadIdx.x;   // 256
    for (int idx = t; idx < KK * HH; idx += 256)
        w1r[idx >> 4][idx & 15] = mlp_w1[(KK + (idx >> 4)) * HH + (idx & 15)];
    for (int idx = t; idx < TAB * HH; idx += 256)
        t1s[idx >> 4][idx & 15] = t1[idx];
    if (t < HH * HH) w2s[t >> 4][t & 15] = mlp_w2[t];
    if (t < KK) {
        float s = fabsf(g_stds[t]) + 0.01f;
        istd_s[t] = 1.0f / s;
        coef_s[t] = 1.0f / (sqrtf(2.0f * 3.14159f) * s);
        mean_s[t] = g_means[t];
    }
    if (t < HH) b2s[t] = mlp_b2[t];
    __syncthreads();

    int bi = blockIdx.x;                    // b*N + i
    int j = t;
    size_t idx = (size_t)bi * NN + j;
    int sp = sp_dist[idx];
    float rd = rd_dist[idx];
    float x = g_mulp[0] * rd + g_biasp[0];

    float acc[HH];
#pragma unroll
    for (int h = 0; h < HH; h++) acc[h] = t1s[sp][h];

    for (int k = 0; k < KK; k++) {
        float dd = (x - mean_s[k]) * istd_s[k];
        float g = expf(-0.5f * dd * dd) * coef_s[k];
#pragma unroll
        for (int h = 0; h < HH; h++) acc[h] += g * w1r[k][h];
    }
#pragma unroll
    for (int h = 0; h < HH; h++) {
        float a = acc[h];
        acc[h] = 0.5f * a * (1.0f + erff(a * 0.70710678118654752f));
    }

    int b = bi >> 8, i = bi & 255;
#pragma unroll
    for (int h2 = 0; h2 < HH; h2++) {
        float o = b2s[h2];
#pragma unroll
        for (int h = 0; h < HH; h++) o += acc[h] * w2s[h][h2];
        S[(((size_t)(b * HH + h2) * NN + i) * NN) + j] = o;
    }
}

// ---------------- TF32 MMA core: 64x64 tile, BK=32, 128 threads ----------------
__device__ __forceinline__ unsigned f2tf(float f) {
    unsigned u;
    asm("cvt.rna.tf32.f32 %0, %1;" : "=r"(u) : "f"(f));
    return u;
}

// Ag: A + m0*lda (row-major, leading dim lda). Bg: B + n0 (leading dim ldb).
// Accumulates kLen (multiple of 32) K-steps into c.
__device__ __forceinline__ void mma_core(
    const float* __restrict__ Ag, int lda,
    const float* __restrict__ Bg, int ldb, int kLen,
    float (*As)[64][36], float (*Bs)[32][68], float (&c)[2][4][4]) {
    int t = threadIdx.x;
    int warp = t >> 5, lane = t & 31;
    int g = lane >> 2, q = lane & 3;
    int wm = (warp >> 1) * 32, wn = (warp & 1) * 32;

#pragma unroll
    for (int i = 0; i < 2; i++)
#pragma unroll
        for (int j = 0; j < 4; j++)
#pragma unroll
            for (int e = 0; e < 4; e++) c[i][j][e] = 0.f;

    const int KT = kLen / 32;

    auto load_tile = [&](int bufi, int k0) {
#pragma unroll
        for (int i_ = 0; i_ < 4; i_++) {
            int id = t + i_ * 128;
            int row = id >> 3, c4 = id & 7;
            const float* src = Ag + (size_t)row * lda + k0 + c4 * 4;
            unsigned dst = (unsigned)__cvta_generic_to_shared(&As[bufi][row][c4 * 4]);
            asm volatile("cp.async.ca.shared.global [%0], [%1], 16;\n" ::"r"(dst), "l"(src));
        }
#pragma unroll
        for (int i_ = 0; i_ < 4; i_++) {
            int id = t + i_ * 128;
            int row = id >> 4, c4 = id & 15;
            const float* src = Bg + (size_t)(k0 + row) * ldb + c4 * 4;
            unsigned dst = (unsigned)__cvta_generic_to_shared(&Bs[bufi][row][c4 * 4]);
            asm volatile("cp.async.ca.shared.global [%0], [%1], 16;\n" ::"r"(dst), "l"(src));
        }
        asm volatile("cp.async.commit_group;\n" ::);
    };

    load_tile(0, 0);

    for (int kt = 0; kt < KT; kt++) {
        int buf = kt & 1;
        if (kt + 1 < KT) {
            load_tile(buf ^ 1, (kt + 1) * 32);
            asm volatile("cp.async.wait_group 1;\n" ::);
        } else {
            asm volatile("cp.async.wait_group 0;\n" ::);
        }
        __syncthreads();

#pragma unroll
        for (int ks = 0; ks < 4; ks++) {
            unsigned a[2][4], b[4][2];
#pragma unroll
            for (int mt = 0; mt < 2; mt++) {
                int r = wm + mt * 16 + g;
                int k = ks * 8 + q;
                a[mt][0] = f2tf(As[buf][r][k]);
                a[mt][1] = f2tf(As[buf][r + 8][k]);
                a[mt][2] = f2tf(As[buf][r][k + 4]);
                a[mt][3] = f2tf(As[buf][r + 8][k + 4]);
            }
#pragma unroll
            for (int nt = 0; nt < 4; nt++) {
                int n = wn + nt * 8 + g;
                int k = ks * 8 + q;
                b[nt][0] = f2tf(Bs[buf][k][n]);
                b[nt][1] = f2tf(Bs[buf][k + 4][n]);
            }
#pragma unroll
            for (int mt = 0; mt < 2; mt++)
#pragma unroll
                for (int nt = 0; nt < 4; nt++)
                    asm volatile(
                        "mma.sync.aligned.m16n8k8.row.col.f32.tf32.tf32.f32 "
                        "{%0,%1,%2,%3},{%4,%5,%6,%7},{%8,%9},{%0,%1,%2,%3};"
                        : "+f"(c[mt][nt][0]), "+f"(c[mt][nt][1]),
                          "+f"(c[mt][nt][2]), "+f"(c[mt][nt][3])
                        : "r"(a[mt][0]), "r"(a[mt][1]), "r"(a[mt][2]), "r"(a[mt][3]),
                          "r"(b[nt][0]), "r"(b[nt][1]));
        }
        __syncthreads();
    }
}

// ---------------- generic GEMM: MODE 0 plain+bias, 1 relu+bias, 3 raw partial ----
template <int MODE>
__global__ void __launch_bounds__(128) mma_gemm(
    const float* __restrict__ A, const float* __restrict__ B,
    const float* __restrict__ bias, float* __restrict__ C,
    int N, int lda, int ldb, int kLen) {
    __shared__ float As[2][64][36];
    __shared__ float Bs[2][32][68];
    int m0 = blockIdx.y * 64, n0 = blockIdx.x * 64;

    // split-K: blockIdx.z selects the K slice and the partial output plane
    int z = blockIdx.z;
    const float* Ag = A + (size_t)m0 * lda + (size_t)z * kLen;
    const float* Bg = B + (size_t)z * kLen * ldb + n0;
    float* Cg = (MODE == 3) ? C + (size_t)z * gridDim.y * 64 * N : C;

    float c[2][4][4];
    mma_core(Ag, lda, Bg, ldb, kLen, As, Bs, c);

    int t = threadIdx.x;
    int warp = t >> 5, lane = t & 31;
    int g = lane >> 2, q = lane & 3;
    int wm = (warp >> 1) * 32, wn = (warp & 1) * 32;

#pragma unroll
    for (int mt = 0; mt < 2; mt++)
#pragma unroll
        for (int nt = 0; nt < 4; nt++)
#pragma unroll
            for (int e = 0; e < 4; e++) {
                int row = m0 + wm + mt * 16 + g + ((e >= 2) ? 8 : 0);
                int col = n0 + wn + nt * 8 + q * 2 + (e & 1);
                float v = c[mt][nt][e];
                if (MODE != 3) v += bias[col];
                if (MODE == 1) v = fmaxf(v, 0.f);
                Cg[(size_t)row * N + col] = v;
            }
}

// ---------------- fused QKV GEMM: grid (48, 16) ----------------
__global__ void __launch_bounds__(128) qkv_gemm(
    const float* __restrict__ A,
    const float* __restrict__ wq, const float* __restrict__ wk, const float* __restrict__ wv,
    const float* __restrict__ bq, const float* __restrict__ bk, const float* __restrict__ bv,
    float* __restrict__ Qo, float* __restrict__ Ko, float* __restrict__ Vo) {
    __shared__ float As[2][64][36];
    __shared__ float Bs[2][32][68];
    int mat = blockIdx.x >> 4;
    int n0 = (blockIdx.x & 15) * 64, m0 = blockIdx.y * 64;
    const float* B = (mat == 0) ? wq : (mat == 1) ? wk : wv;
    const float* bias = (mat == 0) ? bq : (mat == 1) ? bk : bv;
    float* C = (mat == 0) ? Qo : (mat == 1) ? Ko : Vo;
    float scale = (mat == 0) ? 8.0f : 1.0f;

    const float* Ag = A + (size_t)m0 * FF;
    const float* Bg = B + n0;

    float c[2][4][4];
    mma_core(Ag, FF, Bg, FF, FF, As, Bs, c);

    int t = threadIdx.x;
    int warp = t >> 5, lane = t & 31;
    int g = lane >> 2, q = lane & 3;
    int wm = (warp >> 1) * 32, wn = (warp & 1) * 32;

#pragma unroll
    for (int mt = 0; mt < 2; mt++)
#pragma unroll
        for (int nt = 0; nt < 4; nt++)
#pragma unroll
            for (int e = 0; e < 4; e++) {
                int row = m0 + wm + mt * 16 + g + ((e >= 2) ? 8 : 0);
                int col = n0 + wn + nt * 8 + q * 2 + (e & 1);
                float v = (c[mt][nt][e] + bias[col]) * scale;
                int b_ = row >> 8, ii = row & 255, h = col >> 6, d = col & 63;
                C[(((size_t)(b_ * HH + h) * NN + ii) * DD) + d] = v;
            }
}

// ---------------- scores ----------------
__global__ void scores_kernel(const float* __restrict__ Q, const float* __restrict__ Kp,
                              float* __restrict__ S) {
    int bh = blockIdx.z;
    int i0 = blockIdx.y * 64, j0 = blockIdx.x * 64;
    const float* Qg = Q + (size_t)bh * NN * DD;
    const float* Kg = Kp + (size_t)bh * NN * DD;
    float* Sg = S + (size_t)bh * NN * NN;

    __shared__ float Qs[64][68];
    __shared__ float Ks[64][68];
    int t = threadIdx.x;          // 256
#pragma unroll
    for (int r = 0; r < 4; r++) {
        int idx = t + r * 256;
        int row = idx >> 4;
        int d4 = (idx & 15) * 4;
        float4 qv = *(const float4*)(Qg + (size_t)(i0 + row) * DD + d4);
        Qs[d4 + 0][row] = qv.x; Qs[d4 + 1][row] = qv.y;
        Qs[d4 + 2][row] = qv.z; Qs[d4 + 3][row] = qv.w;
        float4 kv = *(const float4*)(Kg + (size_t)(j0 + row) * DD + d4);
        Ks[d4 + 0][row] = kv.x; Ks[d4 + 1][row] = kv.y;
        Ks[d4 + 2][row] = kv.z; Ks[d4 + 3][row] = kv.w;
    }
    __syncthreads();

    int tx = t & 15, ty = t >> 4;
    float acc[4][4];
#pragma unroll
    for (int i = 0; i < 4; i++)
#pragma unroll
        for (int j = 0; j < 4; j++) acc[i][j] = 0.f;

#pragma unroll 8
    for (int d = 0; d < 64; d++) {
        float4 qr = *(float4*)&Qs[d][ty * 4];
        float4 kr = *(float4*)&Ks[d][tx * 4];
        float qa[4] = {qr.x, qr.y, qr.z, qr.w};
        float ka[4] = {kr.x, kr.y, kr.z, kr.w};
#pragma unroll
        for (int i = 0; i < 4; i++)
#pragma unroll
            for (int j = 0; j < 4; j++) acc[i][j] += qa[i] * ka[j];
    }
#pragma unroll
    for (int i = 0; i < 4; i++) {
        size_t off = (size_t)(i0 + ty * 4 + i) * NN + j0 + tx * 4;
        float4 bv = *(float4*)(Sg + off);
        bv.x += acc[i][0]; bv.y += acc[i][1];
        bv.z += acc[i][2]; bv.w += acc[i][3];
        *(float4*)(Sg + off) = bv;
    }
}

// ---------------- softmax ----------------
__global__ void softmax_kernel(float* __restrict__ S) {
    size_t row = blockIdx.x;
    float* p = S + row * NN;
    int t = threadIdx.x;
    __shared__ float red[256];
    float v = p[t];
    red[t] = v;
    __syncthreads();
#pragma unroll
    for (int s = 128; s > 0; s >>= 1) {
        if (t < s) red[t] = fmaxf(red[t], red[t + s]);
        __syncthreads();
    }
    float m = red[0];
    __syncthreads();
    float e = expf(v - m);
    red[t] = e;
    __syncthreads();
#pragma unroll
    for (int s = 128; s > 0; s >>= 1) {
        if (t < s) red[t] += red[t + s];
        __syncthreads();
    }
    p[t] = e / red[0];
}

// ---------------- PV ----------------
__global__ void pv_kernel(const float* __restrict__ W, const float* __restrict__ V,
                          float* __restrict__ O) {
    int bh = blockIdx.y;
    int b = bh >> 4, h = bh & 15;
    int i0 = blockIdx.x * 64;
    const float* Wg = W + (size_t)bh * NN * NN;
    const float* Vg = V + (size_t)bh * NN * DD;

    __shared__ float Ws[64][68];
    __shared__ float Vs[64][68];
    int t = threadIdx.x, tx = t & 15, ty = t >> 4;
    float acc[4][4];
#pragma unroll
    for (int i = 0; i < 4; i++)
#pragma unroll
        for (int j = 0; j < 4; j++) acc[i][j] = 0.f;

    for (int jc = 0; jc < 4; jc++) {
        int j0 = jc * 64;
#pragma unroll
        for (int r = 0; r < 4; r++) {
            int idx = t + r * 256;
            int row = idx >> 4;
            int c4 = (idx & 15) * 4;
            float4 wv = *(const float4*)(Wg + (size_t)(i0 + row) * NN + j0 + c4);
            Ws[c4 + 0][row] = wv.x; Ws[c4 + 1][row] = wv.y;
            Ws[c4 + 2][row] = wv.z; Ws[c4 + 3][row] = wv.w;
            float4 vv = *(const float4*)(Vg + (size_t)(j0 + row) * DD + c4);
            *(float4*)&Vs[row][c4] = vv;
        }
        __syncthreads();
#pragma unroll 8
        for (int jj = 0; jj < 64; jj++) {
            float4 wr = *(float4*)&Ws[jj][ty * 4];
            float4 vr = *(float4*)&Vs[jj][tx * 4];
            float wa[4] = {wr.x, wr.y, wr.z, wr.w};
            float va[4] = {vr.x, vr.y, vr.z, vr.w};
#pragma unroll
            for (int i = 0; i < 4; i++)
#pragma unroll
                for (int j = 0; j < 4; j++) acc[i][j] += wa[i] * va[j];
        }
        __syncthreads();
    }
#pragma unroll
    for (int i = 0; i < 4; i++) {
        size_t off = (size_t)(b * NN + i0 + ty * 4 + i) * FF + h * DD + tx * 4;
        float4 v = {acc[i][0], acc[i][1], acc[i][2], acc[i][3]};
        *(float4*)&O[off] = v;
    }
}

// ---------------- out = LayerNorm(A + bias + sum_p part[p]) ----------------
template <int P>
__global__ void add_lnp_kernel(const float* __restrict__ A, const float* __restrict__ part,
                               const float* __restrict__ bias,
                               const float* __restrict__ g, const float* __restrict__ be,
                               float* __restrict__ out) {
    int row = blockIdx.x, t = threadIdx.x;
    const float* a = A + (size_t)row * FF;
    __shared__ float red[256];
    float v[4];
    float s = 0.f;
#pragma unroll
    for (int k = 0; k < 4; k++) {
        int c = t + k * 256;
        float acc = a[c] + bias[c];
#pragma unroll
        for (int p = 0; p < P; p++)
            acc += part[(size_t)p * BB * NN * FF + (size_t)row * FF + c];
        v[k] = acc;
        s += acc;
    }
    red[t] = s;
    __syncthreads();
#pragma unroll
    for (int st = 128; st > 0; st >>= 1) {
        if (t < st) red[t] += red[t + st];
        __syncthreads();
    }
    float mean = red[0] * (1.0f / FF);
    __syncthreads();
    float sq = 0.f;
#pragma unroll
    for (int k = 0; k < 4; k++) {
        float d = v[k] - mean;
        sq += d * d;
    }
    red[t] = sq;
    __syncthreads();
#pragma unroll
    for (int st = 128; st > 0; st >>= 1) {
        if (t < st) red[t] += red[t + st];
        __syncthreads();
    }
    float inv = rsqrtf(red[0] * (1.0f / FF) + 1e-5f);
#pragma unroll
    for (int k = 0; k < 4; k++) {
        int c = t + k * 256;
        out[(size_t)row * FF + c] = (v[k] - mean) * inv * g[c] + be[c];
    }
}

// ---------------- launch ----------------
extern "C" void kernel_launch(void* const* d_in, const int* in_sizes, int n_in,
                              void* d_out, int out_size) {
    const float* nfeat      = (const float*)d_in[0];
    const int*   sp_dist    = (const int*)d_in[1];
    const float* rd_dist    = (const float*)d_in[2];
    const float* dist_table = (const float*)d_in[3];
    const float* g_means    = (const float*)d_in[4];
    const float* g_stds     = (const float*)d_in[5];
    const float* g_mul      = (const float*)d_in[6];
    const float* g_biasv    = (const float*)d_in[7];
    const float* mlp_w1     = (const float*)d_in[8];
    const float* mlp_b1     = (const float*)d_in[9];
    const float* mlp_w2     = (const float*)d_in[10];
    const float* mlp_b2     = (const float*)d_in[11];
    const float* wq = (const float*)d_in[12];  const float* bq = (const float*)d_in[13];
    const float* wk = (const float*)d_in[14];  const float* bk = (const float*)d_in[15];
    const float* wv = (const float*)d_in[16];  const float* bv = (const float*)d_in[17];
    const float* wo = (const float*)d_in[18];  const float* bo = (const float*)d_in[19];
    const float* ffn_w1 = (const float*)d_in[20]; const float* ffn_b1 = (const float*)d_in[21];
    const float* ffn_w2 = (const float*)d_in[22]; const float* ffn_b2 = (const float*)d_in[23];
    const float* ln1_g = (const float*)d_in[24]; const float* ln1_b = (const float*)d_in[25];
    const float* ln2_g = (const float*)d_in[26]; const float* ln2_b = (const float*)d_in[27];

    void *pS, *pQ, *pK, *pV, *pAttn, *pX1, *pHid, *pPart, *pT1;
    cudaGetSymbolAddress(&pS, g_S);
    cudaGetSymbolAddress(&pQ, g_q);
    cudaGetSymbolAddress(&pK, g_k);
    cudaGetSymbolAddress(&pV, g_v);
    cudaGetSymbolAddress(&pAttn, g_attn);
    cudaGetSymbolAddress(&pX1, g_x1);
    cudaGetSymbolAddress(&pHid, g_hid);
    cudaGetSymbolAddress(&pPart, g_part);
    cudaGetSymbolAddress(&pT1, g_t1);

    float* S = (float*)pS; float* Q = (float*)pQ; float* Kb = (float*)pK;
    float* V = (float*)pV; float* At = (float*)pAttn;
    float* X1 = (float*)pX1; float* Hd = (float*)pHid;
    float* Pt = (float*)pPart; float* T1 = (float*)pT1;

    // 1. dist-encoder
    t1_kernel<<<1, 512>>>(dist_table, mlp_w1, mlp_b1, T1);
    bias_kernel<<<BB * NN, 256>>>(sp_dist, rd_dist, g_means, g_stds, g_mul, g_biasv,
                                  mlp_w1, mlp_w2, mlp_b2, T1, S);

    // 2. fused QKV projections (q scaled by sqrt(D)=8 per reference)
    qkv_gemm<<<dim3(48, 16), 128>>>(nfeat, wq, wk, wv, bq, bk, bv, Q, Kb, V);

    // 3. attention
    scores_kernel<<<dim3(4, 4, BB * HH), 256>>>(Q, Kb, S);
    softmax_kernel<<<BB * HH * NN, 256>>>(S);
    pv_kernel<<<dim3(4, BB * HH), 256>>>(S, V, At);

    // 4. output projection (split-K=2 partials) + LN1
    mma_gemm<3><<<dim3(16, 16, 2), 128>>>(At, wo, nullptr, Pt, FF, FF, FF, FF / 2);
    add_lnp_kernel<2><<<BB * NN, 256>>>(nfeat, Pt, bo, ln1_g, ln1_b, X1);

    // 5. FFN: w1+relu direct, w2 split-K=4 partials + LN2
    mma_gemm<1><<<dim3(64, 16, 1), 128>>>(X1, ffn_w1, ffn_b1, Hd, HID, FF, HID, FF);
    mma_gemm<3><<<dim3(16, 16, 4), 128>>>(Hd, ffn_w2, nullptr, Pt, FF, HID, FF, HID / 4);
    add_lnp_kernel<4><<<BB * NN, 256>>>(X1, Pt, ffn_b2, ln2_g, ln2_b, (float*)d_out);
}

// round 4
// speedup vs baseline: 4.1849x; 1.1236x over previous
#include <cuda_runtime.h>
#include <cstdint>
#include <cstddef>
#include <math.h>

// Problem constants
#define BB 4
#define NN 256
#define FF 1024
#define HH 16
#define KK 128
#define DD 64
#define HID 4096
#define TAB 32

// ---------------- scratch (device globals; no allocation) ----------------
__device__ float g_S[(size_t)BB * HH * NN * NN];
__device__ float g_q[(size_t)BB * HH * NN * DD];
__device__ float g_k[(size_t)BB * HH * NN * DD];
__device__ float g_v[(size_t)BB * HH * NN * DD];
__device__ float g_attn[(size_t)BB * NN * FF];
__device__ float g_x1[(size_t)BB * NN * FF];
__device__ float g_hid[(size_t)BB * NN * HID];
__device__ float g_part[(size_t)4 * BB * NN * FF];   // split-K partials
__device__ float g_t1[TAB * HH];

// ---------------- T1 precompute ----------------
__global__ void t1_kernel(const float* __restrict__ dist_table,
                          const float* __restrict__ mlp_w1,
                          const float* __restrict__ mlp_b1,
                          float* __restrict__ t1) {
    int t = threadIdx.x;            // 512 threads
    int sp = t >> 4, h = t & 15;
    float s = mlp_b1[h];
    for (int k = 0; k < KK; k++)
        s += dist_table[sp * KK + k] * mlp_w1[k * HH + h];
    t1[t] = s;
}

// ---------------- bias kernel ----------------
__global__ void bias_kernel(const int* __restrict__ sp_dist,
                            const float* __restrict__ rd_dist,
                            const float* __restrict__ g_means,
                            const float* __restrict__ g_stds,
                            const float* __restrict__ g_mulp,
                            const float* __restrict__ g_biasp,
                            const float* __restrict__ mlp_w1,
                            const float* __restrict__ mlp_w2,
                            const float* __restrict__ mlp_b2,
                            const float* __restrict__ t1,
                            float* __restrict__ S) {
    __shared__ float w1r[KK][HH];
    __shared__ float t1s[TAB][HH];
    __shared__ float w2s[HH][HH];
    __shared__ float mean_s[KK], istd_s[KK], coef_s[KK];
    __shared__ float b2s[HH];

    int t = threadIdx.x;   // 256
    for (int idx = t; idx < KK * HH; idx += 256)
        w1r[idx >> 4][idx & 15] = mlp_w1[(KK + (idx >> 4)) * HH + (idx & 15)];
    for (int idx = t; idx < TAB * HH; idx += 256)
        t1s[idx >> 4][idx & 15] = t1[idx];
    if (t < HH * HH) w2s[t >> 4][t & 15] = mlp_w2[t];
    if (t < KK) {
        float s = fabsf(g_stds[t]) + 0.01f;
        istd_s[t] = 1.0f / s;
        coef_s[t] = 1.0f / (sqrtf(2.0f * 3.14159f) * s);
        mean_s[t] = g_means[t];
    }
    if (t < HH) b2s[t] = mlp_b2[t];
    __syncthreads();

    int bi = blockIdx.x;                    // b*N + i
    int j = t;
    size_t idx = (size_t)bi * NN + j;
    int sp = sp_dist[idx];
    float rd = rd_dist[idx];
    float x = g_mulp[0] * rd + g_biasp[0];

    float acc[HH];
#pragma unroll
    for (int h = 0; h < HH; h++) acc[h] = t1s[sp][h];

    for (int k = 0; k < KK; k++) {
        float dd = (x - mean_s[k]) * istd_s[k];
        float g = expf(-0.5f * dd * dd) * coef_s[k];
#pragma unroll
        for (int h = 0; h < HH; h++) acc[h] += g * w1r[k][h];
    }
#pragma unroll
    for (int h = 0; h < HH; h++) {
        float a = acc[h];
        acc[h] = 0.5f * a * (1.0f + erff(a * 0.70710678118654752f));
    }

    int b = bi >> 8, i = bi & 255;
#pragma unroll
    for (int h2 = 0; h2 < HH; h2++) {
        float o = b2s[h2];
#pragma unroll
        for (int h = 0; h < HH; h++) o += acc[h] * w2s[h][h2];
        S[(((size_t)(b * HH + h2) * NN + i) * NN) + j] = o;
    }
}

// ---------------- TF32 helpers ----------------
__device__ __forceinline__ unsigned f2tf(float f) {
    unsigned u;
    asm("cvt.rna.tf32.f32 %0, %1;" : "=r"(u) : "f"(f));
    return u;
}
__device__ __forceinline__ void split_tf(float f, unsigned& hi, unsigned& lo) {
    hi = f2tf(f);
    lo = f2tf(f - __uint_as_float(hi));
}
__device__ __forceinline__ void mma8(float (&c)[4], const unsigned* a, const unsigned* b) {
    asm volatile(
        "mma.sync.aligned.m16n8k8.row.col.f32.tf32.tf32.f32 "
        "{%0,%1,%2,%3},{%4,%5,%6,%7},{%8,%9},{%0,%1,%2,%3};"
        : "+f"(c[0]), "+f"(c[1]), "+f"(c[2]), "+f"(c[3])
        : "r"(a[0]), "r"(a[1]), "r"(a[2]), "r"(a[3]), "r"(b[0]), "r"(b[1]));
}

// ---------------- TF32 MMA core: 64x64 tile, BK=32, 128 threads ----------------
__device__ __forceinline__ void mma_core(
    const float* __restrict__ Ag, int lda,
    const float* __restrict__ Bg, int ldb, int kLen,
    float (*As)[64][36], float (*Bs)[32][68], float (&c)[2][4][4]) {
    int t = threadIdx.x;
    int warp = t >> 5, lane = t & 31;
    int g = lane >> 2, q = lane & 3;
    int wm = (warp >> 1) * 32, wn = (warp & 1) * 32;

#pragma unroll
    for (int i = 0; i < 2; i++)
#pragma unroll
        for (int j = 0; j < 4; j++)
#pragma unroll
            for (int e = 0; e < 4; e++) c[i][j][e] = 0.f;

    const int KT = kLen / 32;

    auto load_tile = [&](int bufi, int k0) {
#pragma unroll
        for (int i_ = 0; i_ < 4; i_++) {
            int id = t + i_ * 128;
            int row = id >> 3, c4 = id & 7;
            const float* src = Ag + (size_t)row * lda + k0 + c4 * 4;
            unsigned dst = (unsigned)__cvta_generic_to_shared(&As[bufi][row][c4 * 4]);
            asm volatile("cp.async.ca.shared.global [%0], [%1], 16;\n" ::"r"(dst), "l"(src));
        }
#pragma unroll
        for (int i_ = 0; i_ < 4; i_++) {
            int id = t + i_ * 128;
            int row = id >> 4, c4 = id & 15;
            const float* src = Bg + (size_t)(k0 + row) * ldb + c4 * 4;
            unsigned dst = (unsigned)__cvta_generic_to_shared(&Bs[bufi][row][c4 * 4]);
            asm volatile("cp.async.ca.shared.global [%0], [%1], 16;\n" ::"r"(dst), "l"(src));
        }
        asm volatile("cp.async.commit_group;\n" ::);
    };

    load_tile(0, 0);

    for (int kt = 0; kt < KT; kt++) {
        int buf = kt & 1;
        if (kt + 1 < KT) {
            load_tile(buf ^ 1, (kt + 1) * 32);
            asm volatile("cp.async.wait_group 1;\n" ::);
        } else {
            asm volatile("cp.async.wait_group 0;\n" ::);
        }
        __syncthreads();

#pragma unroll
        for (int ks = 0; ks < 4; ks++) {
            unsigned a[2][4], b[4][2];
#pragma unroll
            for (int mt = 0; mt < 2; mt++) {
                int r = wm + mt * 16 + g;
                int k = ks * 8 + q;
                a[mt][0] = f2tf(As[buf][r][k]);
                a[mt][1] = f2tf(As[buf][r + 8][k]);
                a[mt][2] = f2tf(As[buf][r][k + 4]);
                a[mt][3] = f2tf(As[buf][r + 8][k + 4]);
            }
#pragma unroll
            for (int nt = 0; nt < 4; nt++) {
                int n = wn + nt * 8 + g;
                int k = ks * 8 + q;
                b[nt][0] = f2tf(Bs[buf][k][n]);
                b[nt][1] = f2tf(Bs[buf][k + 4][n]);
            }
#pragma unroll
            for (int mt = 0; mt < 2; mt++)
#pragma unroll
                for (int nt = 0; nt < 4; nt++)
                    mma8(c[mt][nt], a[mt], b[nt]);
        }
        __syncthreads();
    }
}

// ---------------- generic GEMM: MODE 0 plain+bias, 1 relu+bias, 3 raw partial ----
template <int MODE>
__global__ void __launch_bounds__(128) mma_gemm(
    const float* __restrict__ A, const float* __restrict__ B,
    const float* __restrict__ bias, float* __restrict__ C,
    int N, int lda, int ldb, int kLen) {
    __shared__ float As[2][64][36];
    __shared__ float Bs[2][32][68];
    int m0 = blockIdx.y * 64, n0 = blockIdx.x * 64;

    int z = blockIdx.z;
    const float* Ag = A + (size_t)m0 * lda + (size_t)z * kLen;
    const float* Bg = B + (size_t)z * kLen * ldb + n0;
    float* Cg = (MODE == 3) ? C + (size_t)z * gridDim.y * 64 * N : C;

    float c[2][4][4];
    mma_core(Ag, lda, Bg, ldb, kLen, As, Bs, c);

    int t = threadIdx.x;
    int warp = t >> 5, lane = t & 31;
    int g = lane >> 2, q = lane & 3;
    int wm = (warp >> 1) * 32, wn = (warp & 1) * 32;

#pragma unroll
    for (int mt = 0; mt < 2; mt++)
#pragma unroll
        for (int nt = 0; nt < 4; nt++)
#pragma unroll
            for (int e = 0; e < 4; e++) {
                int row = m0 + wm + mt * 16 + g + ((e >= 2) ? 8 : 0);
                int col = n0 + wn + nt * 8 + q * 2 + (e & 1);
                float v = c[mt][nt][e];
                if (MODE != 3) v += bias[col];
                if (MODE == 1) v = fmaxf(v, 0.f);
                Cg[(size_t)row * N + col] = v;
            }
}

// ---------------- fused QKV GEMM: grid (48, 16) ----------------
__global__ void __launch_bounds__(128) qkv_gemm(
    const float* __restrict__ A,
    const float* __restrict__ wq, const float* __restrict__ wk, const float* __restrict__ wv,
    const float* __restrict__ bq, const float* __restrict__ bk, const float* __restrict__ bv,
    float* __restrict__ Qo, float* __restrict__ Ko, float* __restrict__ Vo) {
    __shared__ float As[2][64][36];
    __shared__ float Bs[2][32][68];
    int mat = blockIdx.x >> 4;
    int n0 = (blockIdx.x & 15) * 64, m0 = blockIdx.y * 64;
    const float* B = (mat == 0) ? wq : (mat == 1) ? wk : wv;
    const float* bias = (mat == 0) ? bq : (mat == 1) ? bk : bv;
    float* C = (mat == 0) ? Qo : (mat == 1) ? Ko : Vo;
    float scale = (mat == 0) ? 8.0f : 1.0f;

    const float* Ag = A + (size_t)m0 * FF;
    const float* Bg = B + n0;

    float c[2][4][4];
    mma_core(Ag, FF, Bg, FF, FF, As, Bs, c);

    int t = threadIdx.x;
    int warp = t >> 5, lane = t & 31;
    int g = lane >> 2, q = lane & 3;
    int wm = (warp >> 1) * 32, wn = (warp & 1) * 32;

#pragma unroll
    for (int mt = 0; mt < 2; mt++)
#pragma unroll
        for (int nt = 0; nt < 4; nt++)
#pragma unroll
            for (int e = 0; e < 4; e++) {
                int row = m0 + wm + mt * 16 + g + ((e >= 2) ? 8 : 0);
                int col = n0 + wn + nt * 8 + q * 2 + (e & 1);
                float v = (c[mt][nt][e] + bias[col]) * scale;
                int b_ = row >> 8, ii = row & 255, h = col >> 6, d = col & 63;
                C[(((size_t)(b_ * HH + h) * NN + ii) * DD) + d] = v;
            }
}

// ---------------- fused flash attention ----------------
// grid (4, 64): blockIdx.x = i-tile (64 rows), blockIdx.y = b*H+h. 128 threads.
// S = Q@K^T (3xTF32, exact-ish) + bias; online softmax; O = P@V (tf32).
#define ATTN_SMEM (3 * 64 * 68 * 4 + 2 * 64 * 4)
__global__ void __launch_bounds__(128) attn_kernel(
    const float* __restrict__ Q, const float* __restrict__ K,
    const float* __restrict__ V, const float* __restrict__ Sb,
    float* __restrict__ O) {
    extern __shared__ float sm[];
    float* Qs  = sm;                 // [64][68]  Q tile  [i][d]
    float* KPs = sm + 64 * 68;       // [64][68]  K^T [d][j], then P [i][j]
    float* Vs  = sm + 2 * 64 * 68;   // [64][68]  V tile [j][d]
    float* red = sm + 3 * 64 * 68;   // [2][64]   cross-warp row reduction

    int bh = blockIdx.y;
    int b = bh >> 4, h = bh & 15;
    int i0 = blockIdx.x * 64;
    const float* Qg = Q + (size_t)bh * NN * DD + (size_t)i0 * DD;
    const float* Kg = K + (size_t)bh * NN * DD;
    const float* Vg = V + (size_t)bh * NN * DD;
    const float* Bg = Sb + (size_t)bh * NN * NN + (size_t)i0 * NN;

    int t = threadIdx.x;
    int warp = t >> 5, lane = t & 31;
    int g = lane >> 2, q = lane & 3;
    int wm = (warp >> 1) * 32, wn = (warp & 1) * 32;

    // load Q tile [64][64]
#pragma unroll
    for (int r = 0; r < 8; r++) {
        int id = t + r * 128;
        int row = id >> 4, c4 = (id & 15) * 4;
        *(float4*)&Qs[row * 68 + c4] = *(const float4*)(Qg + (size_t)row * DD + c4);
    }

    float o[2][4][4];
#pragma unroll
    for (int mt = 0; mt < 2; mt++)
#pragma unroll
        for (int nt = 0; nt < 4; nt++)
#pragma unroll
            for (int e = 0; e < 4; e++) o[mt][nt][e] = 0.f;
    float mrun[4] = {-1e30f, -1e30f, -1e30f, -1e30f};
    float lrun[4] = {0.f, 0.f, 0.f, 0.f};

    for (int jt = 0; jt < 4; jt++) {
        int j0 = jt * 64;
        __syncthreads();    // prior PV reads of KPs/Vs done; Qs ready
        // K^T tile: KPs[d][j] = K[j0+j][d]
#pragma unroll
        for (int r = 0; r < 8; r++) {
            int id = t + r * 128;
            int row = id >> 4, c4 = (id & 15) * 4;
            float4 kv = *(const float4*)(Kg + (size_t)(j0 + row) * DD + c4);
            KPs[(c4 + 0) * 68 + row] = kv.x;
            KPs[(c4 + 1) * 68 + row] = kv.y;
            KPs[(c4 + 2) * 68 + row] = kv.z;
            KPs[(c4 + 3) * 68 + row] = kv.w;
        }
        // V tile: Vs[j][d]
#pragma unroll
        for (int r = 0; r < 8; r++) {
            int id = t + r * 128;
            int row = id >> 4, c4 = (id & 15) * 4;
            *(float4*)&Vs[row * 68 + c4] = *(const float4*)(Vg + (size_t)(j0 + row) * DD + c4);
        }
        __syncthreads();

        // init c with bias fragment
        float c[2][4][4];
#pragma unroll
        for (int mt = 0; mt < 2; mt++)
#pragma unroll
            for (int nt = 0; nt < 4; nt++) {
                int row0 = wm + mt * 16 + g;
                int col = j0 + wn + nt * 8 + q * 2;
                float2 b0 = *(const float2*)(Bg + (size_t)row0 * NN + col);
                float2 b1 = *(const float2*)(Bg + (size_t)(row0 + 8) * NN + col);
                c[mt][nt][0] = b0.x; c[mt][nt][1] = b0.y;
                c[mt][nt][2] = b1.x; c[mt][nt][3] = b1.y;
            }

        // S += Q @ K^T via 3xTF32 (hi*hi + hi*lo + lo*hi)
#pragma unroll
        for (int ks = 0; ks < 8; ks++) {
            unsigned ah[2][4], al[2][4], bh_[4][2], bl[4][2];
#pragma unroll
            for (int mt = 0; mt < 2; mt++) {
                int r = wm + mt * 16 + g;
                int k = ks * 8 + q;
                split_tf(Qs[r * 68 + k],        ah[mt][0], al[mt][0]);
                split_tf(Qs[(r + 8) * 68 + k],  ah[mt][1], al[mt][1]);
                split_tf(Qs[r * 68 + k + 4],    ah[mt][2], al[mt][2]);
                split_tf(Qs[(r + 8) * 68 + k + 4], ah[mt][3], al[mt][3]);
            }
#pragma unroll
            for (int nt = 0; nt < 4; nt++) {
                int n = wn + nt * 8 + g;
                int k = ks * 8 + q;
                split_tf(KPs[k * 68 + n],       bh_[nt][0], bl[nt][0]);
                split_tf(KPs[(k + 4) * 68 + n], bh_[nt][1], bl[nt][1]);
            }
#pragma unroll
            for (int mt = 0; mt < 2; mt++)
#pragma unroll
                for (int nt = 0; nt < 4; nt++) {
                    mma8(c[mt][nt], ah[mt], bh_[nt]);
                    mma8(c[mt][nt], ah[mt], bl[nt]);
                    mma8(c[mt][nt], al[mt], bh_[nt]);
                }
        }

        // ---- online softmax ----
        // row index per thread element: idx = mt*2 + (e>=2); global-local row:
        // rr(idx) = wm + (idx>>1)*16 + (idx&1)*8 + g
        float tmax[4] = {-1e30f, -1e30f, -1e30f, -1e30f};
#pragma unroll
        for (int mt = 0; mt < 2; mt++)
#pragma unroll
            for (int nt = 0; nt < 4; nt++)
#pragma unroll
                for (int e = 0; e < 4; e++)
                    tmax[mt * 2 + (e >> 1)] = fmaxf(tmax[mt * 2 + (e >> 1)], c[mt][nt][e]);
#pragma unroll
        for (int s = 1; s < 4; s <<= 1)
#pragma unroll
            for (int i = 0; i < 4; i++)
                tmax[i] = fmaxf(tmax[i], __shfl_xor_sync(0xffffffffu, tmax[i], s));
        if (q == 0) {
#pragma unroll
            for (int i = 0; i < 4; i++)
                red[(warp & 1) * 64 + wm + (i >> 1) * 16 + (i & 1) * 8 + g] = tmax[i];
        }
        __syncthreads();
        float scale[4];
#pragma unroll
        for (int i = 0; i < 4; i++) {
            int rr = wm + (i >> 1) * 16 + (i & 1) * 8 + g;
            float tm = fmaxf(red[rr], red[64 + rr]);
            float mnew = fmaxf(mrun[i], tm);
            scale[i] = expf(mrun[i] - mnew);
            mrun[i] = mnew;
        }
        __syncthreads();   // red reads done before sum-phase writes

        float tsum[4] = {0.f, 0.f, 0.f, 0.f};
#pragma unroll
        for (int mt = 0; mt < 2; mt++)
#pragma unroll
            for (int nt = 0; nt < 4; nt++)
#pragma unroll
                for (int e = 0; e < 4; e++) {
                    int idx = mt * 2 + (e >> 1);
                    float p = expf(c[mt][nt][e] - mrun[idx]);
                    c[mt][nt][e] = p;
                    tsum[idx] += p;
                }
#pragma unroll
        for (int s = 1; s < 4; s <<= 1)
#pragma unroll
            for (int i = 0; i < 4; i++)
                tsum[i] += __shfl_xor_sync(0xffffffffu, tsum[i], s);
        if (q == 0) {
#pragma unroll
            for (int i = 0; i < 4; i++)
                red[(warp & 1) * 64 + wm + (i >> 1) * 16 + (i & 1) * 8 + g] = tsum[i];
        }
        // write P into KPs (K dead after S-MMA; all threads past it)
#pragma unroll
        for (int mt = 0; mt < 2; mt++)
#pragma unroll
            for (int nt = 0; nt < 4; nt++) {
                int row0 = wm + mt * 16 + g;
                int col = wn + nt * 8 + q * 2;
                KPs[row0 * 68 + col] = c[mt][nt][0];
                KPs[row0 * 68 + col + 1] = c[mt][nt][1];
                KPs[(row0 + 8) * 68 + col] = c[mt][nt][2];
                KPs[(row0 + 8) * 68 + col + 1] = c[mt][nt][3];
            }
        __syncthreads();

#pragma unroll
        for (int i = 0; i < 4; i++) {
            int rr = wm + (i >> 1) * 16 + (i & 1) * 8 + g;
            lrun[i] = lrun[i] * scale[i] + red[rr] + red[64 + rr];
        }
        // rescale O, then O += P @ V (single tf32)
#pragma unroll
        for (int mt = 0; mt < 2; mt++)
#pragma unroll
            for (int nt = 0; nt < 4; nt++)
#pragma unroll
                for (int e = 0; e < 4; e++)
                    o[mt][nt][e] *= scale[mt * 2 + (e >> 1)];
#pragma unroll
        for (int ks = 0; ks < 8; ks++) {
            unsigned a[2][4], bb[4][2];
#pragma unroll
            for (int mt = 0; mt < 2; mt++) {
                int r = wm + mt * 16 + g;
                int k = ks * 8 + q;
                a[mt][0] = f2tf(KPs[r * 68 + k]);
                a[mt][1] = f2tf(KPs[(r + 8) * 68 + k]);
                a[mt][2] = f2tf(KPs[r * 68 + k + 4]);
                a[mt][3] = f2tf(KPs[(r + 8) * 68 + k + 4]);
            }
#pragma unroll
            for (int nt = 0; nt < 4; nt++) {
                int n = wn + nt * 8 + g;
                int k = ks * 8 + q;
                bb[nt][0] = f2tf(Vs[k * 68 + n]);
                bb[nt][1] = f2tf(Vs[(k + 4) * 68 + n]);
            }
#pragma unroll
            for (int mt = 0; mt < 2; mt++)
#pragma unroll
                for (int nt = 0; nt < 4; nt++)
                    mma8(o[mt][nt], a[mt], bb[nt]);
        }
    }

    // epilogue: O /= l, write to attn concat [b][i][h*64+d]
    float* Og = O + ((size_t)(b * NN + i0)) * FF + h * DD;
#pragma unroll
    for (int mt = 0; mt < 2; mt++) {
        float il0 = 1.0f / lrun[mt * 2];
        float il1 = 1.0f / lrun[mt * 2 + 1];
#pragma unroll
        for (int nt = 0; nt < 4; nt++) {
            int row0 = wm + mt * 16 + g;
            int col = wn + nt * 8 + q * 2;
            float2 v0 = {o[mt][nt][0] * il0, o[mt][nt][1] * il0};
            *(float2*)(Og + (size_t)row0 * FF + col) = v0;
            float2 v1 = {o[mt][nt][2] * il1, o[mt][nt][3] * il1};
            *(float2*)(Og + (size_t)(row0 + 8) * FF + col) = v1;
        }
    }
}

// ---------------- out = LayerNorm(A + bias + sum_p part[p]) ----------------
template <int P>
__global__ void add_lnp_kernel(const float* __restrict__ A, const float* __restrict__ part,
                               const float* __restrict__ bias,
                               const float* __restrict__ g, const float* __restrict__ be,
                               float* __restrict__ out) {
    int row = blockIdx.x, t = threadIdx.x;
    const float* a = A + (size_t)row * FF;
    __shared__ float red[256];
    float v[4];
    float s = 0.f;
#pragma unroll
    for (int k = 0; k < 4; k++) {
        int c = t + k * 256;
        float acc = a[c] + bias[c];
#pragma unroll
        for (int p = 0; p < P; p++)
            acc += part[(size_t)p * BB * NN * FF + (size_t)row * FF + c];
        v[k] = acc;
        s += acc;
    }
    red[t] = s;
    __syncthreads();
#pragma unroll
    for (int st = 128; st > 0; st >>= 1) {
        if (t < st) red[t] += red[t + st];
        __syncthreads();
    }
    float mean = red[0] * (1.0f / FF);
    __syncthreads();
    float sq = 0.f;
#pragma unroll
    for (int k = 0; k < 4; k++) {
        float d = v[k] - mean;
        sq += d * d;
    }
    red[t] = sq;
    __syncthreads();
#pragma unroll
    for (int st = 128; st > 0; st >>= 1) {
        if (t < st) red[t] += red[t + st];
        __syncthreads();
    }
    float inv = rsqrtf(red[0] * (1.0f / FF) + 1e-5f);
#pragma unroll
    for (int k = 0; k < 4; k++) {
        int c = t + k * 256;
        out[(size_t)row * FF + c] = (v[k] - mean) * inv * g[c] + be[c];
    }
}

// ---------------- launch ----------------
extern "C" void kernel_launch(void* const* d_in, const int* in_sizes, int n_in,
                              void* d_out, int out_size) {
    const float* nfeat      = (const float*)d_in[0];
    const int*   sp_dist    = (const int*)d_in[1];
    const float* rd_dist    = (const float*)d_in[2];
    const float* dist_table = (const float*)d_in[3];
    const float* g_means    = (const float*)d_in[4];
    const float* g_stds     = (const float*)d_in[5];
    const float* g_mul      = (const float*)d_in[6];
    const float* g_biasv    = (const float*)d_in[7];
    const float* mlp_w1     = (const float*)d_in[8];
    const float* mlp_b1     = (const float*)d_in[9];
    const float* mlp_w2     = (const float*)d_in[10];
    const float* mlp_b2     = (const float*)d_in[11];
    const float* wq = (const float*)d_in[12];  const float* bq = (const float*)d_in[13];
    const float* wk = (const float*)d_in[14];  const float* bk = (const float*)d_in[15];
    const float* wv = (const float*)d_in[16];  const float* bv = (const float*)d_in[17];
    const float* wo = (const float*)d_in[18];  const float* bo = (const float*)d_in[19];
    const float* ffn_w1 = (const float*)d_in[20]; const float* ffn_b1 = (const float*)d_in[21];
    const float* ffn_w2 = (const float*)d_in[22]; const float* ffn_b2 = (const float*)d_in[23];
    const float* ln1_g = (const float*)d_in[24]; const float* ln1_b = (const float*)d_in[25];
    const float* ln2_g = (const float*)d_in[26]; const float* ln2_b = (const float*)d_in[27];

    void *pS, *pQ, *pK, *pV, *pAttn, *pX1, *pHid, *pPart, *pT1;
    cudaGetSymbolAddress(&pS, g_S);
    cudaGetSymbolAddress(&pQ, g_q);
    cudaGetSymbolAddress(&pK, g_k);
    cudaGetSymbolAddress(&pV, g_v);
    cudaGetSymbolAddress(&pAttn, g_attn);
    cudaGetSymbolAddress(&pX1, g_x1);
    cudaGetSymbolAddress(&pHid, g_hid);
    cudaGetSymbolAddress(&pPart, g_part);
    cudaGetSymbolAddress(&pT1, g_t1);

    float* S = (float*)pS; float* Q = (float*)pQ; float* Kb = (float*)pK;
    float* V = (float*)pV; float* At = (float*)pAttn;
    float* X1 = (float*)pX1; float* Hd = (float*)pHid;
    float* Pt = (float*)pPart; float* T1 = (float*)pT1;

    static bool attr_done = false;
    if (!attr_done) {
        cudaFuncSetAttribute(attn_kernel, cudaFuncAttributeMaxDynamicSharedMemorySize,
                             ATTN_SMEM);
        attr_done = true;
    }

    // 1. dist-encoder
    t1_kernel<<<1, 512>>>(dist_table, mlp_w1, mlp_b1, T1);
    bias_kernel<<<BB * NN, 256>>>(sp_dist, rd_dist, g_means, g_stds, g_mul, g_biasv,
                                  mlp_w1, mlp_w2, mlp_b2, T1, S);

    // 2. fused QKV projections (q scaled by sqrt(D)=8 per reference)
    qkv_gemm<<<dim3(48, 16), 128>>>(nfeat, wq, wk, wv, bq, bk, bv, Q, Kb, V);

    // 3. fused flash attention (scores + bias + softmax + PV)
    attn_kernel<<<dim3(4, BB * HH), 128, ATTN_SMEM>>>(Q, Kb, V, S, At);

    // 4. output projection (split-K=2 partials) + LN1
    mma_gemm<3><<<dim3(16, 16, 2), 128>>>(At, wo, nullptr, Pt, FF, FF, FF, FF / 2);
    add_lnp_kernel<2><<<BB * NN, 256>>>(nfeat, Pt, bo, ln1_g, ln1_b, X1);

    // 5. FFN: w1+relu direct, w2 split-K=4 partials + LN2
    mma_gemm<1><<<dim3(64, 16, 1), 128>>>(X1, ffn_w1, ffn_b1, Hd, HID, FF, HID, FF);
    mma_gemm<3><<<dim3(16, 16, 4), 128>>>(Hd, ffn_w2, nullptr, Pt, FF, HID, FF, HID / 4);
    add_lnp_kernel<4><<<BB * NN, 256>>>(X1, Pt, ffn_b2, ln2_g, ln2_b, (float*)d_out);
}

// round 5
// speedup vs baseline: 4.4403x; 1.0610x over previous
#include <cuda_runtime.h>
#include <cstdint>
#include <cstddef>
#include <math.h>

// Problem constants
#define BB 4
#define NN 256
#define FF 1024
#define HH 16
#define KK 128
#define DD 64
#define HID 4096
#define TAB 32

// ---------------- scratch (device globals; no allocation) ----------------
__device__ float g_S[(size_t)BB * HH * NN * NN];
__device__ float g_q[(size_t)BB * HH * NN * DD];
__device__ float g_k[(size_t)BB * HH * NN * DD];
__device__ float g_v[(size_t)BB * HH * NN * DD];
__device__ float g_attn[(size_t)BB * NN * FF];
__device__ float g_x1[(size_t)BB * NN * FF];
__device__ float g_hid[(size_t)BB * NN * HID];
__device__ float g_part[(size_t)4 * BB * NN * FF];   // split-K partials
__device__ float g_t1[TAB * HH];

// ---------------- T1 precompute ----------------
__global__ void t1_kernel(const float* __restrict__ dist_table,
                          const float* __restrict__ mlp_w1,
                          const float* __restrict__ mlp_b1,
                          float* __restrict__ t1) {
    int t = threadIdx.x;            // 512 threads
    int sp = t >> 4, h = t & 15;
    float s = mlp_b1[h];
    for (int k = 0; k < KK; k++)
        s += dist_table[sp * KK + k] * mlp_w1[k * HH + h];
    t1[t] = s;
}

// ---------------- bias kernel ----------------
__global__ void bias_kernel(const int* __restrict__ sp_dist,
                            const float* __restrict__ rd_dist,
                            const float* __restrict__ g_means,
                            const float* __restrict__ g_stds,
                            const float* __restrict__ g_mulp,
                            const float* __restrict__ g_biasp,
                            const float* __restrict__ mlp_w1,
                            const float* __restrict__ mlp_w2,
                            const float* __restrict__ mlp_b2,
                            const float* __restrict__ t1,
                            float* __restrict__ S) {
    __shared__ float w1r[KK][HH];
    __shared__ float t1s[TAB][HH];
    __shared__ float w2s[HH][HH];
    __shared__ float mean_s[KK], istd_s[KK], coef_s[KK];
    __shared__ float b2s[HH];

    int t = threadIdx.x;   // 256
    for (int idx = t; idx < KK * HH; idx += 256)
        w1r[idx >> 4][idx & 15] = mlp_w1[(KK + (idx >> 4)) * HH + (idx & 15)];
    for (int idx = t; idx < TAB * HH; idx += 256)
        t1s[idx >> 4][idx & 15] = t1[idx];
    if (t < HH * HH) w2s[t >> 4][t & 15] = mlp_w2[t];
    if (t < KK) {
        float s = fabsf(g_stds[t]) + 0.01f;
        istd_s[t] = 1.0f / s;
        coef_s[t] = 1.0f / (sqrtf(2.0f * 3.14159f) * s);
        mean_s[t] = g_means[t];
    }
    if (t < HH) b2s[t] = mlp_b2[t];
    __syncthreads();

    int bi = blockIdx.x;                    // b*N + i
    int j = t;
    size_t idx = (size_t)bi * NN + j;
    int sp = sp_dist[idx];
    float rd = rd_dist[idx];
    float x = g_mulp[0] * rd + g_biasp[0];

    float acc[HH];
#pragma unroll
    for (int h = 0; h < HH; h++) acc[h] = t1s[sp][h];

    for (int k = 0; k < KK; k++) {
        float dd = (x - mean_s[k]) * istd_s[k];
        float g = expf(-0.5f * dd * dd) * coef_s[k];
#pragma unroll
        for (int h = 0; h < HH; h++) acc[h] += g * w1r[k][h];
    }
#pragma unroll
    for (int h = 0; h < HH; h++) {
        float a = acc[h];
        acc[h] = 0.5f * a * (1.0f + erff(a * 0.70710678118654752f));
    }

    int b = bi >> 8, i = bi & 255;
#pragma unroll
    for (int h2 = 0; h2 < HH; h2++) {
        float o = b2s[h2];
#pragma unroll
        for (int h = 0; h < HH; h++) o += acc[h] * w2s[h][h2];
        S[(((size_t)(b * HH + h2) * NN + i) * NN) + j] = o;
    }
}

// ---------------- TF32 helpers ----------------
__device__ __forceinline__ unsigned f2tf(float f) {
    unsigned u;
    asm("cvt.rna.tf32.f32 %0, %1;" : "=r"(u) : "f"(f));
    return u;
}
__device__ __forceinline__ void split_tf(float f, unsigned& hi, unsigned& lo) {
    hi = f2tf(f);
    lo = f2tf(f - __uint_as_float(hi));
}
__device__ __forceinline__ void mma8(float (&c)[4], const unsigned* a, const unsigned* b) {
    asm volatile(
        "mma.sync.aligned.m16n8k8.row.col.f32.tf32.tf32.f32 "
        "{%0,%1,%2,%3},{%4,%5,%6,%7},{%8,%9},{%0,%1,%2,%3};"
        : "+f"(c[0]), "+f"(c[1]), "+f"(c[2]), "+f"(c[3])
        : "r"(a[0]), "r"(a[1]), "r"(a[2]), "r"(a[3]), "r"(b[0]), "r"(b[1]));
}

// ---------------- TF32 MMA core: 64x64 tile, BK=32, 128 threads ----------------
__device__ __forceinline__ void mma_core(
    const float* __restrict__ Ag, int lda,
    const float* __restrict__ Bg, int ldb, int kLen,
    float (*As)[64][36], float (*Bs)[32][68], float (&c)[2][4][4]) {
    int t = threadIdx.x;
    int warp = t >> 5, lane = t & 31;
    int g = lane >> 2, q = lane & 3;
    int wm = (warp >> 1) * 32, wn = (warp & 1) * 32;

#pragma unroll
    for (int i = 0; i < 2; i++)
#pragma unroll
        for (int j = 0; j < 4; j++)
#pragma unroll
            for (int e = 0; e < 4; e++) c[i][j][e] = 0.f;

    const int KT = kLen / 32;

    auto load_tile = [&](int bufi, int k0) {
#pragma unroll
        for (int i_ = 0; i_ < 4; i_++) {
            int id = t + i_ * 128;
            int row = id >> 3, c4 = id & 7;
            const float* src = Ag + (size_t)row * lda + k0 + c4 * 4;
            unsigned dst = (unsigned)__cvta_generic_to_shared(&As[bufi][row][c4 * 4]);
            asm volatile("cp.async.ca.shared.global [%0], [%1], 16;\n" ::"r"(dst), "l"(src));
        }
#pragma unroll
        for (int i_ = 0; i_ < 4; i_++) {
            int id = t + i_ * 128;
            int row = id >> 4, c4 = id & 15;
            const float* src = Bg + (size_t)(k0 + row) * ldb + c4 * 4;
            unsigned dst = (unsigned)__cvta_generic_to_shared(&Bs[bufi][row][c4 * 4]);
            asm volatile("cp.async.ca.shared.global [%0], [%1], 16;\n" ::"r"(dst), "l"(src));
        }
        asm volatile("cp.async.commit_group;\n" ::);
    };

    load_tile(0, 0);

    for (int kt = 0; kt < KT; kt++) {
        int buf = kt & 1;
        if (kt + 1 < KT) {
            load_tile(buf ^ 1, (kt + 1) * 32);
            asm volatile("cp.async.wait_group 1;\n" ::);
        } else {
            asm volatile("cp.async.wait_group 0;\n" ::);
        }
        __syncthreads();

#pragma unroll
        for (int ks = 0; ks < 4; ks++) {
            unsigned a[2][4], b[4][2];
#pragma unroll
            for (int mt = 0; mt < 2; mt++) {
                int r = wm + mt * 16 + g;
                int k = ks * 8 + q;
                a[mt][0] = f2tf(As[buf][r][k]);
                a[mt][1] = f2tf(As[buf][r + 8][k]);
                a[mt][2] = f2tf(As[buf][r][k + 4]);
                a[mt][3] = f2tf(As[buf][r + 8][k + 4]);
            }
#pragma unroll
            for (int nt = 0; nt < 4; nt++) {
                int n = wn + nt * 8 + g;
                int k = ks * 8 + q;
                b[nt][0] = f2tf(Bs[buf][k][n]);
                b[nt][1] = f2tf(Bs[buf][k + 4][n]);
            }
#pragma unroll
            for (int mt = 0; mt < 2; mt++)
#pragma unroll
                for (int nt = 0; nt < 4; nt++)
                    mma8(c[mt][nt], a[mt], b[nt]);
        }
        __syncthreads();
    }
}

// ---------------- generic GEMM: MODE 0 plain+bias, 1 relu+bias, 3 raw partial ----
template <int MODE>
__global__ void __launch_bounds__(128) mma_gemm(
    const float* __restrict__ A, const float* __restrict__ B,
    const float* __restrict__ bias, float* __restrict__ C,
    int N, int lda, int ldb, int kLen) {
    __shared__ float As[2][64][36];
    __shared__ float Bs[2][32][68];
    int m0 = blockIdx.y * 64, n0 = blockIdx.x * 64;

    int z = blockIdx.z;
    const float* Ag = A + (size_t)m0 * lda + (size_t)z * kLen;
    const float* Bg = B + (size_t)z * kLen * ldb + n0;
    float* Cg = (MODE == 3) ? C + (size_t)z * gridDim.y * 64 * N : C;

    float c[2][4][4];
    mma_core(Ag, lda, Bg, ldb, kLen, As, Bs, c);

    int t = threadIdx.x;
    int warp = t >> 5, lane = t & 31;
    int g = lane >> 2, q = lane & 3;
    int wm = (warp >> 1) * 32, wn = (warp & 1) * 32;

#pragma unroll
    for (int mt = 0; mt < 2; mt++)
#pragma unroll
        for (int nt = 0; nt < 4; nt++)
#pragma unroll
            for (int e = 0; e < 4; e++) {
                int row = m0 + wm + mt * 16 + g + ((e >= 2) ? 8 : 0);
                int col = n0 + wn + nt * 8 + q * 2 + (e & 1);
                float v = c[mt][nt][e];
                if (MODE != 3) v += bias[col];
                if (MODE == 1) v = fmaxf(v, 0.f);
                Cg[(size_t)row * N + col] = v;
            }
}

// ---------------- fused QKV GEMM: grid (48, 16) ----------------
__global__ void __launch_bounds__(128) qkv_gemm(
    const float* __restrict__ A,
    const float* __restrict__ wq, const float* __restrict__ wk, const float* __restrict__ wv,
    const float* __restrict__ bq, const float* __restrict__ bk, const float* __restrict__ bv,
    float* __restrict__ Qo, float* __restrict__ Ko, float* __restrict__ Vo) {
    __shared__ float As[2][64][36];
    __shared__ float Bs[2][32][68];
    int mat = blockIdx.x >> 4;
    int n0 = (blockIdx.x & 15) * 64, m0 = blockIdx.y * 64;
    const float* B = (mat == 0) ? wq : (mat == 1) ? wk : wv;
    const float* bias = (mat == 0) ? bq : (mat == 1) ? bk : bv;
    float* C = (mat == 0) ? Qo : (mat == 1) ? Ko : Vo;
    float scale = (mat == 0) ? 8.0f : 1.0f;

    const float* Ag = A + (size_t)m0 * FF;
    const float* Bg = B + n0;

    float c[2][4][4];
    mma_core(Ag, FF, Bg, FF, FF, As, Bs, c);

    int t = threadIdx.x;
    int warp = t >> 5, lane = t & 31;
    int g = lane >> 2, q = lane & 3;
    int wm = (warp >> 1) * 32, wn = (warp & 1) * 32;

#pragma unroll
    for (int mt = 0; mt < 2; mt++)
#pragma unroll
        for (int nt = 0; nt < 4; nt++)
#pragma unroll
            for (int e = 0; e < 4; e++) {
                int row = m0 + wm + mt * 16 + g + ((e >= 2) ? 8 : 0);
                int col = n0 + wn + nt * 8 + q * 2 + (e & 1);
                float v = (c[mt][nt][e] + bias[col]) * scale;
                int b_ = row >> 8, ii = row & 255, h = col >> 6, d = col & 63;
                C[(((size_t)(b_ * HH + h) * NN + ii) * DD) + d] = v;
            }
}

// ---------------- fused flash attention, 32-row i-tiles ----------------
// grid (8, 64): blockIdx.x = i-tile (32 rows), blockIdx.y = b*H+h. 128 threads.
// Warps 2x2 over the 32x64 S tile: warp tile 16x32.
#define ATTN_SMEM ((32 * 68 + 2 * 64 * 68 + 64) * 4)
__global__ void __launch_bounds__(128) attn_kernel(
    const float* __restrict__ Q, const float* __restrict__ K,
    const float* __restrict__ V, const float* __restrict__ Sb,
    float* __restrict__ O) {
    extern __shared__ float sm[];
    float* Qs  = sm;                        // [32][68]  Q tile  [i][d]
    float* KPs = sm + 32 * 68;              // [64][68]  K^T [d][j], then P [i][j]
    float* Vs  = sm + 32 * 68 + 64 * 68;    // [64][68]  V tile [j][d]
    float* red = sm + 32 * 68 + 2 * 64 * 68; // [2][32]  cross-warp row reduction

    int bh = blockIdx.y;
    int b = bh >> 4, h = bh & 15;
    int i0 = blockIdx.x * 32;
    const float* Qg = Q + (size_t)bh * NN * DD + (size_t)i0 * DD;
    const float* Kg = K + (size_t)bh * NN * DD;
    const float* Vg = V + (size_t)bh * NN * DD;
    const float* Bg = Sb + (size_t)bh * NN * NN + (size_t)i0 * NN;

    int t = threadIdx.x;
    int warp = t >> 5, lane = t & 31;
    int g = lane >> 2, q = lane & 3;
    int wm = (warp >> 1) * 16, wn = (warp & 1) * 32;
    int r0 = wm + g, r1 = wm + g + 8;

    // load Q tile [32][64]
#pragma unroll
    for (int r = 0; r < 4; r++) {
        int id = t + r * 128;
        int row = id >> 4, c4 = (id & 15) * 4;
        *(float4*)&Qs[row * 68 + c4] = *(const float4*)(Qg + (size_t)row * DD + c4);
    }

    float o[4][4];
#pragma unroll
    for (int nt = 0; nt < 4; nt++)
#pragma unroll
        for (int e = 0; e < 4; e++) o[nt][e] = 0.f;
    float mrun[2] = {-1e30f, -1e30f};
    float lrun[2] = {0.f, 0.f};

    for (int jt = 0; jt < 4; jt++) {
        int j0 = jt * 64;
        __syncthreads();    // prior PV reads of KPs/Vs done; Qs ready
        // K^T tile: KPs[d][j] = K[j0+j][d]
#pragma unroll
        for (int r = 0; r < 8; r++) {
            int id = t + r * 128;
            int row = id >> 4, c4 = (id & 15) * 4;
            float4 kv = *(const float4*)(Kg + (size_t)(j0 + row) * DD + c4);
            KPs[(c4 + 0) * 68 + row] = kv.x;
            KPs[(c4 + 1) * 68 + row] = kv.y;
            KPs[(c4 + 2) * 68 + row] = kv.z;
            KPs[(c4 + 3) * 68 + row] = kv.w;
        }
        // V tile: Vs[j][d]
#pragma unroll
        for (int r = 0; r < 8; r++) {
            int id = t + r * 128;
            int row = id >> 4, c4 = (id & 15) * 4;
            *(float4*)&Vs[row * 68 + c4] = *(const float4*)(Vg + (size_t)(j0 + row) * DD + c4);
        }
        __syncthreads();

        // init c with bias fragment
        float c[4][4];
#pragma unroll
        for (int nt = 0; nt < 4; nt++) {
            int col = j0 + wn + nt * 8 + q * 2;
            float2 b0 = *(const float2*)(Bg + (size_t)r0 * NN + col);
            float2 b1 = *(const float2*)(Bg + (size_t)r1 * NN + col);
            c[nt][0] = b0.x; c[nt][1] = b0.y;
            c[nt][2] = b1.x; c[nt][3] = b1.y;
        }

        // S += Q @ K^T via 3xTF32 (hi*hi + hi*lo + lo*hi)
#pragma unroll
        for (int ks = 0; ks < 8; ks++) {
            int k = ks * 8 + q;
            unsigned ah[4], al[4], bh_[4][2], bl[4][2];
            split_tf(Qs[r0 * 68 + k],     ah[0], al[0]);
            split_tf(Qs[r1 * 68 + k],     ah[1], al[1]);
            split_tf(Qs[r0 * 68 + k + 4], ah[2], al[2]);
            split_tf(Qs[r1 * 68 + k + 4], ah[3], al[3]);
#pragma unroll
            for (int nt = 0; nt < 4; nt++) {
                int n = wn + nt * 8 + g;
                split_tf(KPs[k * 68 + n],       bh_[nt][0], bl[nt][0]);
                split_tf(KPs[(k + 4) * 68 + n], bh_[nt][1], bl[nt][1]);
            }
#pragma unroll
            for (int nt = 0; nt < 4; nt++) {
                mma8(c[nt], ah, bh_[nt]);
                mma8(c[nt], ah, bl[nt]);
                mma8(c[nt], al, bh_[nt]);
            }
        }

        // ---- online softmax ----
        float tmax[2] = {-1e30f, -1e30f};
#pragma unroll
        for (int nt = 0; nt < 4; nt++)
#pragma unroll
            for (int e = 0; e < 4; e++)
                tmax[e >> 1] = fmaxf(tmax[e >> 1], c[nt][e]);
#pragma unroll
        for (int s = 1; s < 4; s <<= 1)
#pragma unroll
            for (int i = 0; i < 2; i++)
                tmax[i] = fmaxf(tmax[i], __shfl_xor_sync(0xffffffffu, tmax[i], s));
        if (q == 0) {
            red[(warp & 1) * 32 + r0] = tmax[0];
            red[(warp & 1) * 32 + r1] = tmax[1];
        }
        __syncthreads();
        float scale[2];
#pragma unroll
        for (int i = 0; i < 2; i++) {
            int rr = wm + i * 8 + g;
            float tm = fmaxf(red[rr], red[32 + rr]);
            float mnew = fmaxf(mrun[i], tm);
            scale[i] = expf(mrun[i] - mnew);
            mrun[i] = mnew;
        }
        __syncthreads();   // red reads done before sum-phase writes

        float tsum[2] = {0.f, 0.f};
#pragma unroll
        for (int nt = 0; nt < 4; nt++)
#pragma unroll
            for (int e = 0; e < 4; e++) {
                float p = expf(c[nt][e] - mrun[e >> 1]);
                c[nt][e] = p;
                tsum[e >> 1] += p;
            }
#pragma unroll
        for (int s = 1; s < 4; s <<= 1)
#pragma unroll
            for (int i = 0; i < 2; i++)
                tsum[i] += __shfl_xor_sync(0xffffffffu, tsum[i], s);
        if (q == 0) {
            red[(warp & 1) * 32 + r0] = tsum[0];
            red[(warp & 1) * 32 + r1] = tsum[1];
        }
        // write P into KPs (K dead after S-MMA; all threads past it)
#pragma unroll
        for (int nt = 0; nt < 4; nt++) {
            int col = wn + nt * 8 + q * 2;
            KPs[r0 * 68 + col]     = c[nt][0];
            KPs[r0 * 68 + col + 1] = c[nt][1];
            KPs[r1 * 68 + col]     = c[nt][2];
            KPs[r1 * 68 + col + 1] = c[nt][3];
        }
        __syncthreads();

#pragma unroll
        for (int i = 0; i < 2; i++) {
            int rr = wm + i * 8 + g;
            lrun[i] = lrun[i] * scale[i] + red[rr] + red[32 + rr];
        }
        // rescale O, then O += P @ V (single tf32)
#pragma unroll
        for (int nt = 0; nt < 4; nt++)
#pragma unroll
            for (int e = 0; e < 4; e++)
                o[nt][e] *= scale[e >> 1];
#pragma unroll
        for (int ks = 0; ks < 8; ks++) {
            int k = ks * 8 + q;
            unsigned a[4], bb[4][2];
            a[0] = f2tf(KPs[r0 * 68 + k]);
            a[1] = f2tf(KPs[r1 * 68 + k]);
            a[2] = f2tf(KPs[r0 * 68 + k + 4]);
            a[3] = f2tf(KPs[r1 * 68 + k + 4]);
#pragma unroll
            for (int nt = 0; nt < 4; nt++) {
                int n = wn + nt * 8 + g;
                bb[nt][0] = f2tf(Vs[k * 68 + n]);
                bb[nt][1] = f2tf(Vs[(k + 4) * 68 + n]);
            }
#pragma unroll
            for (int nt = 0; nt < 4; nt++)
                mma8(o[nt], a, bb[nt]);
        }
    }

    // epilogue: O /= l, write to attn concat [b][i][h*64+d]
    float* Og = O + ((size_t)(b * NN + i0)) * FF + h * DD;
    float il0 = 1.0f / lrun[0];
    float il1 = 1.0f / lrun[1];
#pragma unroll
    for (int nt = 0; nt < 4; nt++) {
        int col = wn + nt * 8 + q * 2;
        float2 v0 = {o[nt][0] * il0, o[nt][1] * il0};
        *(float2*)(Og + (size_t)r0 * FF + col) = v0;
        float2 v1 = {o[nt][2] * il1, o[nt][3] * il1};
        *(float2*)(Og + (size_t)r1 * FF + col) = v1;
    }
}

// ---------------- out = LayerNorm(A + bias + sum_p part[p]) ----------------
template <int P>
__global__ void add_lnp_kernel(const float* __restrict__ A, const float* __restrict__ part,
                               const float* __restrict__ bias,
                               const float* __restrict__ g, const float* __restrict__ be,
                               float* __restrict__ out) {
    int row = blockIdx.x, t = threadIdx.x;
    const float* a = A + (size_t)row * FF;
    __shared__ float red[256];
    float v[4];
    float s = 0.f;
#pragma unroll
    for (int k = 0; k < 4; k++) {
        int c = t + k * 256;
        float acc = a[c] + bias[c];
#pragma unroll
        for (int p = 0; p < P; p++)
            acc += part[(size_t)p * BB * NN * FF + (size_t)row * FF + c];
        v[k] = acc;
        s += acc;
    }
    red[t] = s;
    __syncthreads();
#pragma unroll
    for (int st = 128; st > 0; st >>= 1) {
        if (t < st) red[t] += red[t + st];
        __syncthreads();
    }
    float mean = red[0] * (1.0f / FF);
    __syncthreads();
    float sq = 0.f;
#pragma unroll
    for (int k = 0; k < 4; k++) {
        float d = v[k] - mean;
        sq += d * d;
    }
    red[t] = sq;
    __syncthreads();
#pragma unroll
    for (int st = 128; st > 0; st >>= 1) {
        if (t < st) red[t] += red[t + st];
        __syncthreads();
    }
    float inv = rsqrtf(red[0] * (1.0f / FF) + 1e-5f);
#pragma unroll
    for (int k = 0; k < 4; k++) {
        int c = t + k * 256;
        out[(size_t)row * FF + c] = (v[k] - mean) * inv * g[c] + be[c];
    }
}

// ---------------- launch ----------------
extern "C" void kernel_launch(void* const* d_in, const int* in_sizes, int n_in,
                              void* d_out, int out_size) {
    const float* nfeat      = (const float*)d_in[0];
    const int*   sp_dist    = (const int*)d_in[1];
    const float* rd_dist    = (const float*)d_in[2];
    const float* dist_table = (const float*)d_in[3];
    const float* g_means    = (const float*)d_in[4];
    const float* g_stds     = (const float*)d_in[5];
    const float* g_mul      = (const float*)d_in[6];
    const float* g_biasv    = (const float*)d_in[7];
    const float* mlp_w1     = (const float*)d_in[8];
    const float* mlp_b1     = (const float*)d_in[9];
    const float* mlp_w2     = (const float*)d_in[10];
    const float* mlp_b2     = (const float*)d_in[11];
    const float* wq = (const float*)d_in[12];  const float* bq = (const float*)d_in[13];
    const float* wk = (const float*)d_in[14];  const float* bk = (const float*)d_in[15];
    const float* wv = (const float*)d_in[16];  const float* bv = (const float*)d_in[17];
    const float* wo = (const float*)d_in[18];  const float* bo = (const float*)d_in[19];
    const float* ffn_w1 = (const float*)d_in[20]; const float* ffn_b1 = (const float*)d_in[21];
    const float* ffn_w2 = (const float*)d_in[22]; const float* ffn_b2 = (const float*)d_in[23];
    const float* ln1_g = (const float*)d_in[24]; const float* ln1_b = (const float*)d_in[25];
    const float* ln2_g = (const float*)d_in[26]; const float* ln2_b = (const float*)d_in[27];

    void *pS, *pQ, *pK, *pV, *pAttn, *pX1, *pHid, *pPart, *pT1;
    cudaGetSymbolAddress(&pS, g_S);
    cudaGetSymbolAddress(&pQ, g_q);
    cudaGetSymbolAddress(&pK, g_k);
    cudaGetSymbolAddress(&pV, g_v);
    cudaGetSymbolAddress(&pAttn, g_attn);
    cudaGetSymbolAddress(&pX1, g_x1);
    cudaGetSymbolAddress(&pHid, g_hid);
    cudaGetSymbolAddress(&pPart, g_part);
    cudaGetSymbolAddress(&pT1, g_t1);

    float* S = (float*)pS; float* Q = (float*)pQ; float* Kb = (float*)pK;
    float* V = (float*)pV; float* At = (float*)pAttn;
    float* X1 = (float*)pX1; float* Hd = (float*)pHid;
    float* Pt = (float*)pPart; float* T1 = (float*)pT1;

    static cudaStream_t s1;
    static cudaEvent_t evFork, evJoin;
    static bool init_done = false;
    if (!init_done) {
        cudaFuncSetAttribute(attn_kernel, cudaFuncAttributeMaxDynamicSharedMemorySize,
                             ATTN_SMEM);
        cudaStreamCreateWithFlags(&s1, cudaStreamNonBlocking);
        cudaEventCreateWithFlags(&evFork, cudaEventDisableTiming);
        cudaEventCreateWithFlags(&evJoin, cudaEventDisableTiming);
        init_done = true;
    }

    // fork: dist-encoder chain on s1, QKV on main stream (independent)
    cudaEventRecord(evFork, 0);
    cudaStreamWaitEvent(s1, evFork, 0);
    t1_kernel<<<1, 512, 0, s1>>>(dist_table, mlp_w1, mlp_b1, T1);
    bias_kernel<<<BB * NN, 256, 0, s1>>>(sp_dist, rd_dist, g_means, g_stds, g_mul,
                                         g_biasv, mlp_w1, mlp_w2, mlp_b2, T1, S);
    cudaEventRecord(evJoin, s1);

    // QKV projections on main stream (q scaled by sqrt(D)=8 per reference)
    qkv_gemm<<<dim3(48, 16), 128>>>(nfeat, wq, wk, wv, bq, bk, bv, Q, Kb, V);

    // join: attention needs both bias (s1) and QKV (main)
    cudaStreamWaitEvent(0, evJoin, 0);
    attn_kernel<<<dim3(8, BB * HH), 128, ATTN_SMEM>>>(Q, Kb, V, S, At);

    // output projection (split-K=4 partials) + LN1
    mma_gemm<3><<<dim3(16, 16, 4), 128>>>(At, wo, nullptr, Pt, FF, FF, FF, FF / 4);
    add_lnp_kernel<4><<<BB * NN, 256>>>(nfeat, Pt, bo, ln1_g, ln1_b, X1);

    // FFN: w1+relu direct, w2 split-K=4 partials + LN2
    mma_gemm<1><<<dim3(64, 16, 1), 128>>>(X1, ffn_w1, ffn_b1, Hd, HID, FF, HID, FF);
    mma_gemm<3><<<dim3(16, 16, 4), 128>>>(Hd, ffn_w2, nullptr, Pt, FF, HID, FF, HID / 4);
    add_lnp_kernel<4><<<BB * NN, 256>>>(X1, Pt, ffn_b2, ln2_g, ln2_b, (float*)d_out);
}